// round 1
// baseline (speedup 1.0000x reference)
#include <cuda_runtime.h>
#include <math.h>

#define CD  256
#define HWD 4096
#define BD  4

// ---------------- device scratch (no allocations allowed) ----------------
__device__ __align__(16) float g_wnT[3][CD * CD];        // standardized weights, transposed [c][o]
__device__ __align__(16) float g_q[BD * CD * HWD];
__device__ __align__(16) float g_k[BD * CD * HWD];
__device__ __align__(16) float g_v[BD * CD * HWD];

// ---------------- 1) weight standardization (writes W^T) ----------------
// grid: 256 blocks (one per output channel o), 256 threads (one per input c)
__global__ void ws_kernel(const float* __restrict__ w,
                          const float* __restrict__ gain,
                          int set)
{
    int o = blockIdx.x;
    int c = threadIdx.x;
    float v = w[o * CD + c];

    float s = v, s2 = v * v;
    #pragma unroll
    for (int off = 16; off; off >>= 1) {
        s  += __shfl_xor_sync(0xffffffffu, s,  off);
        s2 += __shfl_xor_sync(0xffffffffu, s2, off);
    }
    __shared__ float red[16];
    int warp = c >> 5, lane = c & 31;
    if (lane == 0) { red[warp] = s; red[8 + warp] = s2; }
    __syncthreads();
    if (c == 0) {
        float ts = 0.f, ts2 = 0.f;
        #pragma unroll
        for (int i = 0; i < 8; i++) { ts += red[i]; ts2 += red[8 + i]; }
        red[0] = ts; red[8] = ts2;
    }
    __syncthreads();
    float mean = red[0] * (1.0f / CD);
    float var  = (red[8] - (float)CD * mean * mean) * (1.0f / (CD - 1));  // ddof=1
    float scale = rsqrtf(fmaxf(var * (float)CD, 1e-4f)) * gain[o];
    g_wnT[set][c * CD + o] = (v - mean) * scale;
}

// ---------------- 2) QKV GEMM:  out[o,i] = sum_c wnT[c,o] * x[c,i] + bias[o] ----------------
// grid: (HW/64, C/64, 12) where z = set*4 + batch ; 256 threads, 64x64 tile, 4x4 micro
__global__ __launch_bounds__(256) void qkv_kernel(
    const float* __restrict__ a_in, const float* __restrict__ b_in,
    const float* __restrict__ bq, const float* __restrict__ bk, const float* __restrict__ bv)
{
    __shared__ __align__(16) float As[64 * 64];
    __shared__ __align__(16) float Bs[64 * 64];

    int set = blockIdx.z >> 2;     // 0=q, 1=k, 2=v
    int bat = blockIdx.z & 3;
    const float* X    = ((set == 1) ? b_in : a_in) + bat * CD * HWD;
    const float* bias = (set == 0) ? bq : (set == 1) ? bk : bv;
    float* OUT = ((set == 0) ? g_q : (set == 1) ? g_k : g_v) + bat * CD * HWD;
    const float* Wt = g_wnT[set];

    int i0 = blockIdx.x * 64, o0 = blockIdx.y * 64;
    int tid = threadIdx.x, ty = tid >> 4, tx = tid & 15;

    float acc[4][4] = {};

    for (int k0 = 0; k0 < CD; k0 += 64) {
        #pragma unroll
        for (int t = 0; t < 4; t++) {
            int f = tid + t * 256;
            int r = f >> 4, col = (f & 15) << 2;
            *(float4*)&As[r * 64 + col] = *(const float4*)&Wt[(k0 + r) * CD + o0 + col];
            *(float4*)&Bs[r * 64 + col] = *(const float4*)&X[(size_t)(k0 + r) * HWD + i0 + col];
        }
        __syncthreads();
        #pragma unroll 16
        for (int cc = 0; cc < 64; cc++) {
            float4 af = *(const float4*)&As[cc * 64 + (ty << 2)];
            float4 bf = *(const float4*)&Bs[cc * 64 + (tx << 2)];
            float av[4] = {af.x, af.y, af.z, af.w};
            float bv2[4] = {bf.x, bf.y, bf.z, bf.w};
            #pragma unroll
            for (int r = 0; r < 4; r++)
                #pragma unroll
                for (int j = 0; j < 4; j++)
                    acc[r][j] = fmaf(av[r], bv2[j], acc[r][j]);
        }
        __syncthreads();
    }

    #pragma unroll
    for (int r = 0; r < 4; r++) {
        float bb = bias[o0 + (ty << 2) + r];
        float4 o4 = make_float4(acc[r][0] + bb, acc[r][1] + bb, acc[r][2] + bb, acc[r][3] + bb);
        *(float4*)&OUT[(size_t)(o0 + (ty << 2) + r) * HWD + i0 + (tx << 2)] = o4;
    }
}

// ---------------- 3) fused masked attention + blend ----------------
// grid: (HW/64, B), 256 threads. Flash-style over j tiles of 64.
// logits = mask_i * (q_i . k_j); softmax over j; O = V P^T; out = a*m + g*(1-m)*O
__global__ __launch_bounds__(256, 2) void attn_kernel(
    const float* __restrict__ a_in, const float* __restrict__ cm,
    const float* __restrict__ gamma_p, float* __restrict__ out)
{
    __shared__ __align__(16) float bufA[64 * 64];  // q chunk [c][i] / v chunk (xor-swizzled [j][c])
    __shared__ __align__(16) float bufB[64 * 65];  // k chunk [c][j] (stride 64) then P [j][i] (stride 65)
    __shared__ float m_s[64];

    int bat = blockIdx.y;
    int i0  = blockIdx.x * 64;
    int tid = threadIdx.x, ty = tid >> 4, tx = tid & 15;

    const float* Q = g_q + (size_t)bat * CD * HWD;
    const float* K = g_k + (size_t)bat * CD * HWD;
    const float* V = g_v + (size_t)bat * CD * HWD;

    if (tid < 64) {
        int i = i0 + tid;
        int h = i >> 6, w = i & 63;
        m_s[tid] = cm[bat * 1024 + (h >> 1) * 32 + (w >> 1)];  // nearest 2x upsample
    }
    __syncthreads();

    float mrow[4];
    #pragma unroll
    for (int ii = 0; ii < 4; ii++) mrow[ii] = m_s[(ty << 2) + ii];

    float rmax[4], rsum[4];
    #pragma unroll
    for (int ii = 0; ii < 4; ii++) { rmax[ii] = -INFINITY; rsum[ii] = 0.f; }
    float acc_o[4][4][4] = {};   // [chunk][cf][ii] : channel = chunk*64 + tx*4 + cf, query = ty*4 + ii

    #pragma unroll 1
    for (int j0 = 0; j0 < HWD; j0 += 64) {
        // ---- S = Q^T K on this 64x64 tile ----
        float s[4][4] = {};
        #pragma unroll 1
        for (int ch = 0; ch < 4; ch++) {
            __syncthreads();
            #pragma unroll
            for (int t = 0; t < 4; t++) {
                int f = tid + t * 256;
                int r = f >> 4, col = (f & 15) << 2;
                *(float4*)&bufA[r * 64 + col] = *(const float4*)&Q[(size_t)(ch * 64 + r) * HWD + i0 + col];
                *(float4*)&bufB[r * 64 + col] = *(const float4*)&K[(size_t)(ch * 64 + r) * HWD + j0 + col];
            }
            __syncthreads();
            #pragma unroll 16
            for (int cc = 0; cc < 64; cc++) {
                float4 qf = *(const float4*)&bufA[cc * 64 + (ty << 2)];
                float4 kf = *(const float4*)&bufB[cc * 64 + (tx << 2)];
                float qa[4] = {qf.x, qf.y, qf.z, qf.w};
                float ka[4] = {kf.x, kf.y, kf.z, kf.w};
                #pragma unroll
                for (int ii = 0; ii < 4; ii++)
                    #pragma unroll
                    for (int jj = 0; jj < 4; jj++)
                        s[ii][jj] = fmaf(qa[ii], ka[jj], s[ii][jj]);
            }
        }
        __syncthreads();   // all k reads done; bufB free for P

        // ---- online softmax with per-row temperature mask ----
        #pragma unroll
        for (int ii = 0; ii < 4; ii++) {
            float m = mrow[ii];
            float l[4];
            #pragma unroll
            for (int jj = 0; jj < 4; jj++) l[jj] = m * s[ii][jj];
            float tmax = fmaxf(fmaxf(l[0], l[1]), fmaxf(l[2], l[3]));
            #pragma unroll
            for (int off = 1; off < 16; off <<= 1)
                tmax = fmaxf(tmax, __shfl_xor_sync(0xffffffffu, tmax, off));
            float nmax  = fmaxf(rmax[ii], tmax);
            float alpha = __expf(rmax[ii] - nmax);
            rmax[ii] = nmax;
            float p[4], ps = 0.f;
            #pragma unroll
            for (int jj = 0; jj < 4; jj++) { p[jj] = __expf(l[jj] - nmax); ps += p[jj]; }
            #pragma unroll
            for (int off = 1; off < 16; off <<= 1)
                ps += __shfl_xor_sync(0xffffffffu, ps, off);
            rsum[ii] = rsum[ii] * alpha + ps;
            #pragma unroll
            for (int ch = 0; ch < 4; ch++)
                #pragma unroll
                for (int cf = 0; cf < 4; cf++)
                    acc_o[ch][cf][ii] *= alpha;
            #pragma unroll
            for (int jj = 0; jj < 4; jj++)
                bufB[((tx << 2) + jj) * 65 + (ty << 2) + ii] = p[jj];   // P[j][i], stride 65
        }
        __syncthreads();

        // ---- O += V P^T ----
        #pragma unroll 1
        for (int ch = 0; ch < 4; ch++) {
            #pragma unroll
            for (int t = 0; t < 4; t++) {
                int f = tid + t * 256;
                int r = f >> 4, col = (f & 15) << 2;     // r = local c, col = local j
                float4 v4 = *(const float4*)&V[(size_t)(ch * 64 + r) * HWD + j0 + col];
                float va[4] = {v4.x, v4.y, v4.z, v4.w};
                #pragma unroll
                for (int d = 0; d < 4; d++) {
                    int jj = col + d;
                    bufA[jj * 64 + ((((r >> 2) ^ (jj & 15)) << 2) | (r & 3))] = va[d];  // xor-swizzled [j][c]
                }
            }
            __syncthreads();
            #pragma unroll 8
            for (int j = 0; j < 64; j++) {
                float4 vf = *(const float4*)&bufA[j * 64 + ((tx ^ (j & 15)) << 2)];
                float va[4] = {vf.x, vf.y, vf.z, vf.w};
                float pv[4];
                #pragma unroll
                for (int ii = 0; ii < 4; ii++) pv[ii] = bufB[j * 65 + (ty << 2) + ii];
                #pragma unroll
                for (int cf = 0; cf < 4; cf++)
                    #pragma unroll
                    for (int ii = 0; ii < 4; ii++)
                        acc_o[ch][cf][ii] = fmaf(va[cf], pv[ii], acc_o[ch][cf][ii]);
            }
            __syncthreads();
        }
    }

    // ---- epilogue: normalize, blend with a, write ----
    float gamma = gamma_p[0];
    float inv[4];
    #pragma unroll
    for (int ii = 0; ii < 4; ii++) inv[ii] = 1.0f / rsum[ii];

    #pragma unroll
    for (int ch = 0; ch < 4; ch++) {
        #pragma unroll
        for (int cf = 0; cf < 4; cf++) {
            int c = ch * 64 + (tx << 2) + cf;
            size_t base = ((size_t)bat * CD + c) * HWD + i0 + (ty << 2);
            float4 a4 = *(const float4*)&a_in[base];
            float aa[4] = {a4.x, a4.y, a4.z, a4.w};
            float rr[4];
            #pragma unroll
            for (int ii = 0; ii < 4; ii++) {
                float m = mrow[ii];
                float o = acc_o[ch][cf][ii] * inv[ii];
                rr[ii] = aa[ii] * m + gamma * (1.0f - m) * o;
            }
            *(float4*)&out[base] = make_float4(rr[0], rr[1], rr[2], rr[3]);
        }
    }
}

// ---------------- launch ----------------
extern "C" void kernel_launch(void* const* d_in, const int* in_sizes, int n_in,
                              void* d_out, int out_size)
{
    const float* a  = (const float*)d_in[0];
    const float* b  = (const float*)d_in[1];
    const float* c  = (const float*)d_in[2];
    const float* wq = (const float*)d_in[3];
    const float* bq = (const float*)d_in[4];
    const float* gq = (const float*)d_in[5];
    const float* wk = (const float*)d_in[6];
    const float* bk = (const float*)d_in[7];
    const float* gk = (const float*)d_in[8];
    const float* wv = (const float*)d_in[9];
    const float* bv = (const float*)d_in[10];
    const float* gv = (const float*)d_in[11];
    const float* gm = (const float*)d_in[12];
    float* out = (float*)d_out;

    ws_kernel<<<CD, CD>>>(wq, gq, 0);
    ws_kernel<<<CD, CD>>>(wk, gk, 1);
    ws_kernel<<<CD, CD>>>(wv, gv, 2);

    dim3 g1(HWD / 64, CD / 64, 12);
    qkv_kernel<<<g1, 256>>>(a, b, bq, bk, bv);

    dim3 g2(HWD / 64, BD);
    attn_kernel<<<g2, 256>>>(a, c, gm, out);
}

// round 6
// speedup vs baseline: 2.3760x; 2.3760x over previous
#include <cuda_runtime.h>
#include <cuda_fp16.h>
#include <cstdint>
#include <math.h>

typedef unsigned int u32;

#define CDIM  256
#define HWDIM 4096
#define BDIM  4

// ---------------- device scratch ----------------
__device__ __align__(16) float  g_wnT[3][CDIM * CDIM];     // standardized weights, [c][o]
__device__ __align__(16) __half g_qh[BDIM * HWDIM * CDIM]; // q hi  [b][i][c]
__device__ __align__(16) __half g_ql[BDIM * HWDIM * CDIM]; // q lo
__device__ __align__(16) __half g_kh[BDIM * HWDIM * CDIM]; // k hi  [b][j][c]
__device__ __align__(16) __half g_kl[BDIM * HWDIM * CDIM];
__device__ __align__(16) __half g_vh[BDIM * CDIM * HWDIM]; // v hi  [b][c][j]
__device__ __align__(16) __half g_vl[BDIM * CDIM * HWDIM];

// ---------------- mma / ldmatrix helpers ----------------
__device__ __forceinline__ void ldsm4(u32* r, const void* p) {
    u32 addr = (u32)__cvta_generic_to_shared(p);
    asm volatile("ldmatrix.sync.aligned.m8n8.x4.shared.b16 {%0,%1,%2,%3}, [%4];"
                 : "=r"(r[0]), "=r"(r[1]), "=r"(r[2]), "=r"(r[3]) : "r"(addr));
}
__device__ __forceinline__ void mma16816(float* d, const u32* a, u32 b0, u32 b1) {
    asm volatile("mma.sync.aligned.m16n8k16.row.col.f32.f16.f16.f32 "
                 "{%0,%1,%2,%3}, {%4,%5,%6,%7}, {%8,%9}, {%0,%1,%2,%3};"
                 : "+f"(d[0]), "+f"(d[1]), "+f"(d[2]), "+f"(d[3])
                 : "r"(a[0]), "r"(a[1]), "r"(a[2]), "r"(a[3]), "r"(b0), "r"(b1));
}

// ---------------- 1) weight standardization ----------------
__global__ void ws_kernel(const float* __restrict__ w,
                          const float* __restrict__ gain, int set)
{
    int o = blockIdx.x, c = threadIdx.x;
    float v = w[o * CDIM + c];
    float s = v, s2 = v * v;
    #pragma unroll
    for (int off = 16; off; off >>= 1) {
        s  += __shfl_xor_sync(0xffffffffu, s,  off);
        s2 += __shfl_xor_sync(0xffffffffu, s2, off);
    }
    __shared__ float red[16];
    int warp = c >> 5, lane = c & 31;
    if (lane == 0) { red[warp] = s; red[8 + warp] = s2; }
    __syncthreads();
    if (c == 0) {
        float ts = 0.f, ts2 = 0.f;
        #pragma unroll
        for (int i = 0; i < 8; i++) { ts += red[i]; ts2 += red[8 + i]; }
        red[0] = ts; red[8] = ts2;
    }
    __syncthreads();
    float mean = red[0] * (1.0f / CDIM);
    float var  = (red[8] - (float)CDIM * mean * mean) * (1.0f / (CDIM - 1));
    float scale = rsqrtf(fmaxf(var * (float)CDIM, 1e-4f)) * gain[o];
    g_wnT[set][c * CDIM + o] = (v - mean) * scale;
}

// ---------------- 2) QKV GEMM -> split fp16 outputs ----------------
__global__ __launch_bounds__(256) void qkv_kernel(
    const float* __restrict__ a_in, const float* __restrict__ b_in,
    const float* __restrict__ bq, const float* __restrict__ bk, const float* __restrict__ bv)
{
    __shared__ __align__(16) float As[64 * 64];
    __shared__ __align__(16) float Bs[64 * 64];

    int set = blockIdx.z >> 2;
    int bat = blockIdx.z & 3;
    const float* X    = ((set == 1) ? b_in : a_in) + bat * CDIM * HWDIM;
    const float* bias = (set == 0) ? bq : (set == 1) ? bk : bv;
    const float* Wt = g_wnT[set];

    int i0 = blockIdx.x * 64, o0 = blockIdx.y * 64;
    int tid = threadIdx.x, ty = tid >> 4, tx = tid & 15;

    float acc[4][4] = {};
    for (int k0 = 0; k0 < CDIM; k0 += 64) {
        #pragma unroll
        for (int t = 0; t < 4; t++) {
            int f = tid + t * 256;
            int r = f >> 4, col = (f & 15) << 2;
            *(float4*)&As[r * 64 + col] = *(const float4*)&Wt[(k0 + r) * CDIM + o0 + col];
            *(float4*)&Bs[r * 64 + col] = *(const float4*)&X[(size_t)(k0 + r) * HWDIM + i0 + col];
        }
        __syncthreads();
        #pragma unroll 16
        for (int cc = 0; cc < 64; cc++) {
            float4 af = *(const float4*)&As[cc * 64 + (ty << 2)];
            float4 bf = *(const float4*)&Bs[cc * 64 + (tx << 2)];
            float av[4] = {af.x, af.y, af.z, af.w};
            float bw[4] = {bf.x, bf.y, bf.z, bf.w};
            #pragma unroll
            for (int r = 0; r < 4; r++)
                #pragma unroll
                for (int j = 0; j < 4; j++)
                    acc[r][j] = fmaf(av[r], bw[j], acc[r][j]);
        }
        __syncthreads();
    }

    if (set == 2) {
        // v: [c][i] layout
        #pragma unroll
        for (int r = 0; r < 4; r++) {
            int o = o0 + (ty << 2) + r;
            float bb = bias[o];
            size_t base = ((size_t)bat * CDIM + o) * HWDIM + i0 + (tx << 2);
            __half hs[4], ls[4];
            #pragma unroll
            for (int j = 0; j < 4; j++) {
                float x = acc[r][j] + bb;
                hs[j] = __float2half_rn(x);
                ls[j] = __float2half_rn(x - __half2float(hs[j]));
            }
            *(__half2*)&g_vh[base]     = __halves2half2(hs[0], hs[1]);
            *(__half2*)&g_vh[base + 2] = __halves2half2(hs[2], hs[3]);
            *(__half2*)&g_vl[base]     = __halves2half2(ls[0], ls[1]);
            *(__half2*)&g_vl[base + 2] = __halves2half2(ls[2], ls[3]);
        }
    } else {
        // q/k: transposed [i][c] layout
        __half* OH = set ? g_kh : g_qh;
        __half* OL = set ? g_kl : g_ql;
        #pragma unroll
        for (int j = 0; j < 4; j++) {
            int i = i0 + (tx << 2) + j;
            size_t base = ((size_t)bat * HWDIM + i) * CDIM + o0 + (ty << 2);
            __half hs[4], ls[4];
            #pragma unroll
            for (int r = 0; r < 4; r++) {
                float x = acc[r][j] + bias[o0 + (ty << 2) + r];
                hs[r] = __float2half_rn(x);
                ls[r] = __float2half_rn(x - __half2float(hs[r]));
            }
            *(__half2*)&OH[base]     = __halves2half2(hs[0], hs[1]);
            *(__half2*)&OH[base + 2] = __halves2half2(hs[2], hs[3]);
            *(__half2*)&OL[base]     = __halves2half2(ls[0], ls[1]);
            *(__half2*)&OL[base + 2] = __halves2half2(ls[2], ls[3]);
        }
    }
}

// ---------------- 3) flash attention on tensor cores ----------------
constexpr int kQS = 264;            // Q smem row stride (halves)
constexpr int kKS = 72;             // K/V/P smem row stride (halves)
constexpr int kOS = 68;             // epilogue O staging stride (floats; 272B, 16B-aligned)
constexpr int kOffQl  = 33792;
constexpr int kOffKh  = 67584;
constexpr int kOffKl  = 76800;
constexpr int kOffPs  = 86016;
constexpr int kOffF32 = 95232;
constexpr int kSmemBytes = 97280;

__global__ __launch_bounds__(256) void attn_kernel(
    const float* __restrict__ a_in, const float* __restrict__ cm,
    const float* __restrict__ gamma_p, float* __restrict__ out)
{
    extern __shared__ char smem[];
    __half* Qh = (__half*)smem;
    __half* Ql = (__half*)(smem + kOffQl);
    __half* Kh = (__half*)(smem + kOffKh);   // K chunk / V chunk (hi)
    __half* Kl = (__half*)(smem + kOffKl);
    __half* Ps = (__half*)(smem + kOffPs);
    float*  m_s     = (float*)(smem + kOffF32);
    float*  rmax_s  = m_s + 64;
    float*  rsum_s  = m_s + 128;
    float*  alpha_s = m_s + 192;
    float*  maxbuf  = m_s + 256;   // [2][64]
    float*  sumbuf  = m_s + 384;   // [2][64]
    float*  Osm     = (float*)smem;  // epilogue staging (reuses Q area), 64 x kOS

    int bat = blockIdx.y;
    int i0  = blockIdx.x * 64;
    int tid = threadIdx.x, lane = tid & 31, wid = tid >> 5;
    int wm = wid & 3, wn = wid >> 2;

    const __half* GQh = g_qh + (size_t)bat * HWDIM * CDIM;
    const __half* GQl = g_ql + (size_t)bat * HWDIM * CDIM;
    const __half* GKh = g_kh + (size_t)bat * HWDIM * CDIM;
    const __half* GKl = g_kl + (size_t)bat * HWDIM * CDIM;
    const __half* GVh = g_vh + (size_t)bat * CDIM * HWDIM;
    const __half* GVl = g_vl + (size_t)bat * CDIM * HWDIM;

    if (tid < 64) {
        int i = i0 + tid;
        m_s[tid] = cm[bat * 1024 + ((i >> 6) >> 1) * 32 + ((i & 63) >> 1)];
        rmax_s[tid] = -INFINITY;
        rsum_s[tid] = 0.f;
    }
    // load resident Q tile (hi + lo)
    #pragma unroll
    for (int t = 0; t < 8; t++) {
        int idx = tid + t * 256;
        int r = idx >> 5, c8 = (idx & 31) << 3;
        size_t gb = (size_t)(i0 + r) * CDIM + c8;
        *(float4*)&Qh[r * kQS + c8] = *(const float4*)&GQh[gb];
        *(float4*)&Ql[r * kQS + c8] = *(const float4*)&GQl[gb];
    }
    __syncthreads();

    int rowA = wm * 16 + (lane >> 2), rowB = rowA + 8;
    float mA = m_s[rowA], mB = m_s[rowB];

    float acc_o[4][4][4];
    #pragma unroll
    for (int c = 0; c < 4; c++)
        #pragma unroll
        for (int t = 0; t < 4; t++)
            #pragma unroll
            for (int e = 0; e < 4; e++) acc_o[c][t][e] = 0.f;

    for (int j0 = 0; j0 < HWDIM; j0 += 64) {
        // ======== S = Q^T K (split fp16, 3 mmas) ========
        float sacc[4][4];
        #pragma unroll
        for (int t = 0; t < 4; t++)
            #pragma unroll
            for (int e = 0; e < 4; e++) sacc[t][e] = 0.f;

        #pragma unroll
        for (int ch = 0; ch < 4; ch++) {
            __syncthreads();
            #pragma unroll
            for (int t = 0; t < 2; t++) {
                int idx = tid + t * 256;
                int r = idx >> 3, c8 = (idx & 7) << 3;
                size_t gb = (size_t)(j0 + r) * CDIM + ch * 64 + c8;
                *(float4*)&Kh[r * kKS + c8] = *(const float4*)&GKh[gb];
                *(float4*)&Kl[r * kKS + c8] = *(const float4*)&GKl[gb];
            }
            __syncthreads();

            int arow = wm * 16 + (lane & 15);
            int acol = ch * 64 + ((lane >> 4) << 3);
            int brow = wn * 32 + (lane & 7) + ((lane >> 4) << 3);
            int bcol = ((lane >> 3) & 1) << 3;
            #pragma unroll
            for (int kk = 0; kk < 4; kk++) {
                u32 qa[4], qb[4];
                ldsm4(qa, &Qh[arow * kQS + acol + kk * 16]);
                ldsm4(qb, &Ql[arow * kQS + acol + kk * 16]);
                #pragma unroll
                for (int t2 = 0; t2 < 2; t2++) {
                    u32 kh4[4], kl4[4];
                    ldsm4(kh4, &Kh[(brow + t2 * 16) * kKS + kk * 16 + bcol]);
                    ldsm4(kl4, &Kl[(brow + t2 * 16) * kKS + kk * 16 + bcol]);
                    mma16816(sacc[t2 * 2 + 0], qa, kh4[0], kh4[1]);
                    mma16816(sacc[t2 * 2 + 0], qa, kl4[0], kl4[1]);
                    mma16816(sacc[t2 * 2 + 0], qb, kh4[0], kh4[1]);
                    mma16816(sacc[t2 * 2 + 1], qa, kh4[2], kh4[3]);
                    mma16816(sacc[t2 * 2 + 1], qa, kl4[2], kl4[3]);
                    mma16816(sacc[t2 * 2 + 1], qb, kh4[2], kh4[3]);
                }
            }
        }

        // ======== online softmax (mask as per-row temperature) ========
        float vmaxA = -INFINITY, vmaxB = -INFINITY;
        #pragma unroll
        for (int t = 0; t < 4; t++) {
            sacc[t][0] *= mA; sacc[t][1] *= mA;
            sacc[t][2] *= mB; sacc[t][3] *= mB;
            vmaxA = fmaxf(vmaxA, fmaxf(sacc[t][0], sacc[t][1]));
            vmaxB = fmaxf(vmaxB, fmaxf(sacc[t][2], sacc[t][3]));
        }
        #pragma unroll
        for (int off = 1; off < 4; off <<= 1) {
            vmaxA = fmaxf(vmaxA, __shfl_xor_sync(0xffffffffu, vmaxA, off));
            vmaxB = fmaxf(vmaxB, __shfl_xor_sync(0xffffffffu, vmaxB, off));
        }
        if ((lane & 3) == 0) {
            maxbuf[wn * 64 + rowA] = vmaxA;
            maxbuf[wn * 64 + rowB] = vmaxB;
        }
        __syncthreads();
        if (tid < 64) {
            float nm = fmaxf(rmax_s[tid], fmaxf(maxbuf[tid], maxbuf[64 + tid]));
            alpha_s[tid] = __expf(rmax_s[tid] - nm);
            rmax_s[tid] = nm;
        }
        __syncthreads();
        float nmA = rmax_s[rowA], nmB = rmax_s[rowB];
        float alA = alpha_s[rowA], alB = alpha_s[rowB];
        float psA = 0.f, psB = 0.f;
        #pragma unroll
        for (int t = 0; t < 4; t++) {
            float p0 = __expf(sacc[t][0] - nmA), p1 = __expf(sacc[t][1] - nmA);
            float p2 = __expf(sacc[t][2] - nmB), p3 = __expf(sacc[t][3] - nmB);
            psA += p0 + p1; psB += p2 + p3;
            int col = wn * 32 + t * 8 + ((lane & 3) << 1);
            *(__half2*)&Ps[rowA * kKS + col] = __floats2half2_rn(p0, p1);
            *(__half2*)&Ps[rowB * kKS + col] = __floats2half2_rn(p2, p3);
        }
        #pragma unroll
        for (int c = 0; c < 4; c++)
            #pragma unroll
            for (int t = 0; t < 4; t++) {
                acc_o[c][t][0] *= alA; acc_o[c][t][1] *= alA;
                acc_o[c][t][2] *= alB; acc_o[c][t][3] *= alB;
            }
        #pragma unroll
        for (int off = 1; off < 4; off <<= 1) {
            psA += __shfl_xor_sync(0xffffffffu, psA, off);
            psB += __shfl_xor_sync(0xffffffffu, psB, off);
        }
        if ((lane & 3) == 0) {
            sumbuf[wn * 64 + rowA] = psA;
            sumbuf[wn * 64 + rowB] = psB;
        }
        __syncthreads();
        if (tid < 64)
            rsum_s[tid] = rsum_s[tid] * alpha_s[tid] + sumbuf[tid] + sumbuf[64 + tid];

        // ======== O += P V^T (p fp16, v split) ========
        u32 pf[4][4];
        {
            int prow = wm * 16 + (lane & 15);
            int pcol = (lane >> 4) << 3;
            #pragma unroll
            for (int kk = 0; kk < 4; kk++)
                ldsm4(pf[kk], &Ps[prow * kKS + kk * 16 + pcol]);
        }
        #pragma unroll
        for (int ch = 0; ch < 4; ch++) {
            __syncthreads();
            #pragma unroll
            for (int t = 0; t < 2; t++) {
                int idx = tid + t * 256;
                int r = idx >> 3, c8 = (idx & 7) << 3;
                size_t gb = (size_t)(ch * 64 + r) * HWDIM + j0 + c8;
                *(float4*)&Kh[r * kKS + c8] = *(const float4*)&GVh[gb];
                *(float4*)&Kl[r * kKS + c8] = *(const float4*)&GVl[gb];
            }
            __syncthreads();
            int brow = wn * 32 + (lane & 7) + ((lane >> 4) << 3);
            int bcol = ((lane >> 3) & 1) << 3;
            #pragma unroll
            for (int kk = 0; kk < 4; kk++) {
                #pragma unroll
                for (int t2 = 0; t2 < 2; t2++) {
                    u32 vh4[4], vl4[4];
                    ldsm4(vh4, &Kh[(brow + t2 * 16) * kKS + kk * 16 + bcol]);
                    ldsm4(vl4, &Kl[(brow + t2 * 16) * kKS + kk * 16 + bcol]);
                    mma16816(acc_o[ch][t2 * 2 + 0], pf[kk], vh4[0], vh4[1]);
                    mma16816(acc_o[ch][t2 * 2 + 0], pf[kk], vl4[0], vl4[1]);
                    mma16816(acc_o[ch][t2 * 2 + 1], pf[kk], vh4[2], vh4[3]);
                    mma16816(acc_o[ch][t2 * 2 + 1], pf[kk], vl4[2], vl4[3]);
                }
            }
        }
    }

    // ======== epilogue: normalize, blend, store ========
    __syncthreads();
    float gamma = gamma_p[0];
    float invA = 1.0f / rsum_s[rowA], invB = 1.0f / rsum_s[rowB];

    #pragma unroll
    for (int ch = 0; ch < 4; ch++) {
        __syncthreads();
        #pragma unroll
        for (int t = 0; t < 4; t++) {
            int c0 = wn * 32 + t * 8 + ((lane & 3) << 1);
            Osm[c0 * kOS + rowA]       = acc_o[ch][t][0] * invA;
            Osm[(c0 + 1) * kOS + rowA] = acc_o[ch][t][1] * invA;
            Osm[c0 * kOS + rowB]       = acc_o[ch][t][2] * invB;
            Osm[(c0 + 1) * kOS + rowB] = acc_o[ch][t][3] * invB;
        }
        __syncthreads();
        int r = tid >> 2, c4 = (tid & 3) << 4;
        size_t gb = ((size_t)bat * CDIM + ch * 64 + r) * HWDIM + i0 + c4;
        #pragma unroll
        for (int u = 0; u < 4; u++) {
            float4 o4 = *(float4*)&Osm[r * kOS + c4 + u * 4];
            float4 a4 = *(const float4*)&a_in[gb + u * 4];
            float ov[4] = {o4.x, o4.y, o4.z, o4.w};
            float av[4] = {a4.x, a4.y, a4.z, a4.w};
            float rr[4];
            #pragma unroll
            for (int e = 0; e < 4; e++) {
                float m = m_s[c4 + u * 4 + e];
                rr[e] = av[e] * m + gamma * (1.0f - m) * ov[e];
            }
            *(float4*)&out[gb + u * 4] = make_float4(rr[0], rr[1], rr[2], rr[3]);
        }
    }
}

// ---------------- launch ----------------
extern "C" void kernel_launch(void* const* d_in, const int* in_sizes, int n_in,
                              void* d_out, int out_size)
{
    const float* a  = (const float*)d_in[0];
    const float* b  = (const float*)d_in[1];
    const float* c  = (const float*)d_in[2];
    const float* wq = (const float*)d_in[3];
    const float* bq = (const float*)d_in[4];
    const float* gq = (const float*)d_in[5];
    const float* wk = (const float*)d_in[6];
    const float* bk = (const float*)d_in[7];
    const float* gk = (const float*)d_in[8];
    const float* wv = (const float*)d_in[9];
    const float* bv = (const float*)d_in[10];
    const float* gv = (const float*)d_in[11];
    const float* gm = (const float*)d_in[12];
    float* out = (float*)d_out;

    cudaFuncSetAttribute(attn_kernel, cudaFuncAttributeMaxDynamicSharedMemorySize, kSmemBytes);

    ws_kernel<<<CDIM, CDIM>>>(wq, gq, 0);
    ws_kernel<<<CDIM, CDIM>>>(wk, gk, 1);
    ws_kernel<<<CDIM, CDIM>>>(wv, gv, 2);

    dim3 g1(HWDIM / 64, CDIM / 64, 12);
    qkv_kernel<<<g1, 256>>>(a, b, bq, bk, bv);

    dim3 g2(HWDIM / 64, BDIM);
    attn_kernel<<<g2, 256, kSmemBytes>>>(a, c, gm, out);
}

// round 7
// speedup vs baseline: 3.5812x; 1.5073x over previous
#include <cuda_runtime.h>
#include <cuda_fp16.h>
#include <cstdint>
#include <math.h>

typedef unsigned int u32;

#define CDIM  256
#define HWDIM 4096
#define BDIM  4

// ---------------- device scratch ----------------
__device__ __align__(16) float  g_wnT[3][CDIM * CDIM];     // standardized weights, [c][o]
__device__ __align__(16) __half g_qh[BDIM * HWDIM * CDIM]; // q hi  [b][i][c]
__device__ __align__(16) __half g_ql[BDIM * HWDIM * CDIM]; // q lo
__device__ __align__(16) __half g_kh[BDIM * HWDIM * CDIM]; // k hi  [b][j][c]
__device__ __align__(16) __half g_kl[BDIM * HWDIM * CDIM];
__device__ __align__(16) __half g_vh[BDIM * CDIM * HWDIM]; // v hi  [b][c][j]
__device__ __align__(16) __half g_vl[BDIM * CDIM * HWDIM];

// ---------------- mma / ldmatrix / cp.async helpers ----------------
__device__ __forceinline__ void ldsm4(u32* r, const void* p) {
    u32 addr = (u32)__cvta_generic_to_shared(p);
    asm volatile("ldmatrix.sync.aligned.m8n8.x4.shared.b16 {%0,%1,%2,%3}, [%4];"
                 : "=r"(r[0]), "=r"(r[1]), "=r"(r[2]), "=r"(r[3]) : "r"(addr));
}
__device__ __forceinline__ void mma16816(float* d, const u32* a, u32 b0, u32 b1) {
    asm volatile("mma.sync.aligned.m16n8k16.row.col.f32.f16.f16.f32 "
                 "{%0,%1,%2,%3}, {%4,%5,%6,%7}, {%8,%9}, {%0,%1,%2,%3};"
                 : "+f"(d[0]), "+f"(d[1]), "+f"(d[2]), "+f"(d[3])
                 : "r"(a[0]), "r"(a[1]), "r"(a[2]), "r"(a[3]), "r"(b0), "r"(b1));
}
__device__ __forceinline__ void cpasync16(u32 smem_dst, const void* gptr) {
    asm volatile("cp.async.cg.shared.global [%0], [%1], 16;" :: "r"(smem_dst), "l"(gptr));
}
__device__ __forceinline__ void cpcommit() { asm volatile("cp.async.commit_group;"); }
__device__ __forceinline__ void cpwait1()  { asm volatile("cp.async.wait_group 1;"); }
__device__ __forceinline__ void cpwait0()  { asm volatile("cp.async.wait_group 0;"); }

// ---------------- 1) weight standardization ----------------
__global__ void ws_kernel(const float* __restrict__ w,
                          const float* __restrict__ gain, int set)
{
    int o = blockIdx.x, c = threadIdx.x;
    float v = w[o * CDIM + c];
    float s = v, s2 = v * v;
    #pragma unroll
    for (int off = 16; off; off >>= 1) {
        s  += __shfl_xor_sync(0xffffffffu, s,  off);
        s2 += __shfl_xor_sync(0xffffffffu, s2, off);
    }
    __shared__ float red[16];
    int warp = c >> 5, lane = c & 31;
    if (lane == 0) { red[warp] = s; red[8 + warp] = s2; }
    __syncthreads();
    if (c == 0) {
        float ts = 0.f, ts2 = 0.f;
        #pragma unroll
        for (int i = 0; i < 8; i++) { ts += red[i]; ts2 += red[8 + i]; }
        red[0] = ts; red[8] = ts2;
    }
    __syncthreads();
    float mean = red[0] * (1.0f / CDIM);
    float var  = (red[8] - (float)CDIM * mean * mean) * (1.0f / (CDIM - 1));
    float scale = rsqrtf(fmaxf(var * (float)CDIM, 1e-4f)) * gain[o];
    g_wnT[set][c * CDIM + o] = (v - mean) * scale;
}

// ---------------- 2) QKV GEMM -> split fp16 outputs ----------------
__global__ __launch_bounds__(256) void qkv_kernel(
    const float* __restrict__ a_in, const float* __restrict__ b_in,
    const float* __restrict__ bq, const float* __restrict__ bk, const float* __restrict__ bv)
{
    __shared__ __align__(16) float As[64 * 64];
    __shared__ __align__(16) float Bs[64 * 64];

    int set = blockIdx.z >> 2;
    int bat = blockIdx.z & 3;
    const float* X    = ((set == 1) ? b_in : a_in) + bat * CDIM * HWDIM;
    const float* bias = (set == 0) ? bq : (set == 1) ? bk : bv;
    const float* Wt = g_wnT[set];

    int i0 = blockIdx.x * 64, o0 = blockIdx.y * 64;
    int tid = threadIdx.x, ty = tid >> 4, tx = tid & 15;

    float acc[4][4] = {};
    for (int k0 = 0; k0 < CDIM; k0 += 64) {
        #pragma unroll
        for (int t = 0; t < 4; t++) {
            int f = tid + t * 256;
            int r = f >> 4, col = (f & 15) << 2;
            *(float4*)&As[r * 64 + col] = *(const float4*)&Wt[(k0 + r) * CDIM + o0 + col];
            *(float4*)&Bs[r * 64 + col] = *(const float4*)&X[(size_t)(k0 + r) * HWDIM + i0 + col];
        }
        __syncthreads();
        #pragma unroll 16
        for (int cc = 0; cc < 64; cc++) {
            float4 af = *(const float4*)&As[cc * 64 + (ty << 2)];
            float4 bf = *(const float4*)&Bs[cc * 64 + (tx << 2)];
            float av[4] = {af.x, af.y, af.z, af.w};
            float bw[4] = {bf.x, bf.y, bf.z, bf.w};
            #pragma unroll
            for (int r = 0; r < 4; r++)
                #pragma unroll
                for (int j = 0; j < 4; j++)
                    acc[r][j] = fmaf(av[r], bw[j], acc[r][j]);
        }
        __syncthreads();
    }

    if (set == 2) {
        #pragma unroll
        for (int r = 0; r < 4; r++) {
            int o = o0 + (ty << 2) + r;
            float bb = bias[o];
            size_t base = ((size_t)bat * CDIM + o) * HWDIM + i0 + (tx << 2);
            __half hs[4], ls[4];
            #pragma unroll
            for (int j = 0; j < 4; j++) {
                float x = acc[r][j] + bb;
                hs[j] = __float2half_rn(x);
                ls[j] = __float2half_rn(x - __half2float(hs[j]));
            }
            *(__half2*)&g_vh[base]     = __halves2half2(hs[0], hs[1]);
            *(__half2*)&g_vh[base + 2] = __halves2half2(hs[2], hs[3]);
            *(__half2*)&g_vl[base]     = __halves2half2(ls[0], ls[1]);
            *(__half2*)&g_vl[base + 2] = __halves2half2(ls[2], ls[3]);
        }
    } else {
        __half* OH = set ? g_kh : g_qh;
        __half* OL = set ? g_kl : g_ql;
        #pragma unroll
        for (int j = 0; j < 4; j++) {
            int i = i0 + (tx << 2) + j;
            size_t base = ((size_t)bat * HWDIM + i) * CDIM + o0 + (ty << 2);
            __half hs[4], ls[4];
            #pragma unroll
            for (int r = 0; r < 4; r++) {
                float x = acc[r][j] + bias[o0 + (ty << 2) + r];
                hs[r] = __float2half_rn(x);
                ls[r] = __float2half_rn(x - __half2float(hs[r]));
            }
            *(__half2*)&OH[base]     = __halves2half2(hs[0], hs[1]);
            *(__half2*)&OH[base + 2] = __halves2half2(hs[2], hs[3]);
            *(__half2*)&OL[base]     = __halves2half2(ls[0], ls[1]);
            *(__half2*)&OL[base + 2] = __halves2half2(ls[2], ls[3]);
        }
    }
}

// ---------------- 3) flash attention, BM=128, cp.async 3-stage pipeline ----------------
constexpr int kBM  = 128;
constexpr int kQS  = 264;              // Q smem row stride (halves)
constexpr int kKS  = 72;               // K/V/P smem row stride (halves)
constexpr int kOS  = 132;              // epilogue O staging stride (floats; 528B, 16B-aligned)
constexpr int kQhBytes    = kBM * kQS * 2;           // 67584
constexpr int kOffQl      = kQhBytes;                // 67584
constexpr int kStageHalf  = 64 * kKS * 2;            // 9216 (one of hi/lo)
constexpr int kStageBytes = 2 * kStageHalf;          // 18432
constexpr int kOffStage   = 2 * kQhBytes;            // 135168
constexpr int kOffPs      = kOffStage + 3 * kStageBytes;   // 190464
constexpr int kOffF32     = kOffPs + kBM * kKS * 2;        // 208896
constexpr int kSmemBytes  = kOffF32 + 4096;                // 212992
constexpr int kChunksPerIter = 8;                    // K0..K3, V0..V3
constexpr int kTotalChunks   = (HWDIM / 64) * kChunksPerIter;  // 512

__global__ __launch_bounds__(512) void attn_kernel(
    const float* __restrict__ a_in, const float* __restrict__ cm,
    const float* __restrict__ gamma_p, float* __restrict__ out)
{
    extern __shared__ char smem[];
    __half* Qh = (__half*)smem;
    __half* Ql = (__half*)(smem + kOffQl);
    __half* Ps = (__half*)(smem + kOffPs);
    float*  m_s     = (float*)(smem + kOffF32);
    float*  rmax_s  = m_s + 128;
    float*  rsum_s  = m_s + 256;
    float*  alpha_s = m_s + 384;
    float*  maxbuf  = m_s + 512;   // [2][128]
    float*  sumbuf  = m_s + 768;   // [2][128]
    float*  Osm     = (float*)smem;  // epilogue staging (reuses Q area), 64 x kOS

    int bat = blockIdx.y;
    int i0  = blockIdx.x * kBM;
    int tid = threadIdx.x, lane = tid & 31, wid = tid >> 5;
    int wm = wid & 7, wn = wid >> 3;

    const __half* GQh = g_qh + (size_t)bat * HWDIM * CDIM;
    const __half* GQl = g_ql + (size_t)bat * HWDIM * CDIM;
    const __half* GKh = g_kh + (size_t)bat * HWDIM * CDIM;
    const __half* GKl = g_kl + (size_t)bat * HWDIM * CDIM;
    const __half* GVh = g_vh + (size_t)bat * CDIM * HWDIM;
    const __half* GVl = g_vl + (size_t)bat * CDIM * HWDIM;

    // ---- chunk prefetch (1 chunk = 64 rows x 64 halves, hi+lo; one commit group) ----
    int cr = tid >> 3, cc8 = (tid & 7) << 3;
    auto issue_chunk = [&](int g) {
        int itj = g >> 3, c = g & 7;
        int j0 = itj * 64;
        const __half *srcH, *srcL;
        if (c < 4) {
            size_t o = (size_t)(j0 + cr) * CDIM + c * 64 + cc8;
            srcH = GKh + o; srcL = GKl + o;
        } else {
            size_t o = (size_t)((c - 4) * 64 + cr) * HWDIM + j0 + cc8;
            srcH = GVh + o; srcL = GVl + o;
        }
        u32 dH = (u32)__cvta_generic_to_shared(smem + kOffStage + (g % 3) * kStageBytes
                                               + (cr * kKS + cc8) * 2);
        cpasync16(dH, srcH);
        cpasync16(dH + kStageHalf, srcL);
        cpcommit();
    };

    issue_chunk(0);
    issue_chunk(1);
    int gi = 2;

    if (tid < kBM) {
        int i = i0 + tid;
        m_s[tid] = cm[bat * 1024 + ((i >> 6) >> 1) * 32 + ((i & 63) >> 1)];
        rmax_s[tid] = -INFINITY;
        rsum_s[tid] = 0.f;
    }
    // resident Q tile (hi + lo)
    #pragma unroll
    for (int t = 0; t < 8; t++) {
        int idx = tid + t * 512;
        int r = idx >> 5, c8 = (idx & 31) << 3;
        size_t gb = (size_t)(i0 + r) * CDIM + c8;
        *(float4*)&Qh[r * kQS + c8] = *(const float4*)&GQh[gb];
        *(float4*)&Ql[r * kQS + c8] = *(const float4*)&GQl[gb];
    }
    __syncthreads();

    int rowA = wm * 16 + (lane >> 2), rowB = rowA + 8;
    float mA = m_s[rowA], mB = m_s[rowB];

    float acc_o[4][4][4];
    #pragma unroll
    for (int c = 0; c < 4; c++)
        #pragma unroll
        for (int t = 0; t < 4; t++)
            #pragma unroll
            for (int e = 0; e < 4; e++) acc_o[c][t][e] = 0.f;

    for (int it = 0; it < HWDIM / 64; it++) {
        // ======== S = Q^T K (split fp16, 3 mmas) ========
        float sacc[4][4];
        #pragma unroll
        for (int t = 0; t < 4; t++)
            #pragma unroll
            for (int e = 0; e < 4; e++) sacc[t][e] = 0.f;

        #pragma unroll
        for (int ch = 0; ch < 4; ch++) {
            int g = it * kChunksPerIter + ch;
            cpwait1();
            __syncthreads();
            if (gi < kTotalChunks) { issue_chunk(gi); gi++; }
            const __half* Kh = (const __half*)(smem + kOffStage + (g % 3) * kStageBytes);
            const __half* Kl = (const __half*)((const char*)Kh + kStageHalf);

            int arow = wm * 16 + (lane & 15);
            int acol = ch * 64 + ((lane >> 4) << 3);
            int brow = wn * 32 + (lane & 7) + ((lane >> 4) << 3);
            int bcol = ((lane >> 3) & 1) << 3;
            #pragma unroll
            for (int kk = 0; kk < 4; kk++) {
                u32 qa[4], qb[4];
                ldsm4(qa, &Qh[arow * kQS + acol + kk * 16]);
                ldsm4(qb, &Ql[arow * kQS + acol + kk * 16]);
                #pragma unroll
                for (int t2 = 0; t2 < 2; t2++) {
                    u32 kh4[4], kl4[4];
                    ldsm4(kh4, &Kh[(brow + t2 * 16) * kKS + kk * 16 + bcol]);
                    ldsm4(kl4, &Kl[(brow + t2 * 16) * kKS + kk * 16 + bcol]);
                    mma16816(sacc[t2 * 2 + 0], qa, kh4[0], kh4[1]);
                    mma16816(sacc[t2 * 2 + 0], qa, kl4[0], kl4[1]);
                    mma16816(sacc[t2 * 2 + 0], qb, kh4[0], kh4[1]);
                    mma16816(sacc[t2 * 2 + 1], qa, kh4[2], kh4[3]);
                    mma16816(sacc[t2 * 2 + 1], qa, kl4[2], kl4[3]);
                    mma16816(sacc[t2 * 2 + 1], qb, kh4[2], kh4[3]);
                }
            }
        }

        // ======== online softmax (mask as per-row temperature) ========
        float vmaxA = -INFINITY, vmaxB = -INFINITY;
        #pragma unroll
        for (int t = 0; t < 4; t++) {
            sacc[t][0] *= mA; sacc[t][1] *= mA;
            sacc[t][2] *= mB; sacc[t][3] *= mB;
            vmaxA = fmaxf(vmaxA, fmaxf(sacc[t][0], sacc[t][1]));
            vmaxB = fmaxf(vmaxB, fmaxf(sacc[t][2], sacc[t][3]));
        }
        #pragma unroll
        for (int off = 1; off < 4; off <<= 1) {
            vmaxA = fmaxf(vmaxA, __shfl_xor_sync(0xffffffffu, vmaxA, off));
            vmaxB = fmaxf(vmaxB, __shfl_xor_sync(0xffffffffu, vmaxB, off));
        }
        if ((lane & 3) == 0) {
            maxbuf[wn * 128 + rowA] = vmaxA;
            maxbuf[wn * 128 + rowB] = vmaxB;
        }
        __syncthreads();
        if (tid < kBM) {
            float nm = fmaxf(rmax_s[tid], fmaxf(maxbuf[tid], maxbuf[128 + tid]));
            alpha_s[tid] = __expf(rmax_s[tid] - nm);
            rmax_s[tid] = nm;
        }
        __syncthreads();
        float nmA = rmax_s[rowA], nmB = rmax_s[rowB];
        float alA = alpha_s[rowA], alB = alpha_s[rowB];
        float psA = 0.f, psB = 0.f;
        #pragma unroll
        for (int t = 0; t < 4; t++) {
            float p0 = __expf(sacc[t][0] - nmA), p1 = __expf(sacc[t][1] - nmA);
            float p2 = __expf(sacc[t][2] - nmB), p3 = __expf(sacc[t][3] - nmB);
            psA += p0 + p1; psB += p2 + p3;
            int col = wn * 32 + t * 8 + ((lane & 3) << 1);
            *(__half2*)&Ps[rowA * kKS + col] = __floats2half2_rn(p0, p1);
            *(__half2*)&Ps[rowB * kKS + col] = __floats2half2_rn(p2, p3);
        }
        #pragma unroll
        for (int c = 0; c < 4; c++)
            #pragma unroll
            for (int t = 0; t < 4; t++) {
                acc_o[c][t][0] *= alA; acc_o[c][t][1] *= alA;
                acc_o[c][t][2] *= alB; acc_o[c][t][3] *= alB;
            }
        #pragma unroll
        for (int off = 1; off < 4; off <<= 1) {
            psA += __shfl_xor_sync(0xffffffffu, psA, off);
            psB += __shfl_xor_sync(0xffffffffu, psB, off);
        }
        if ((lane & 3) == 0) {
            sumbuf[wn * 128 + rowA] = psA;
            sumbuf[wn * 128 + rowB] = psB;
        }
        __syncthreads();
        if (tid < kBM)
            rsum_s[tid] = rsum_s[tid] * alpha_s[tid] + sumbuf[tid] + sumbuf[128 + tid];

        // ======== O += P V^T (p fp16, v split) ========
        u32 pf[4][4];
        {
            int prow = wm * 16 + (lane & 15);
            int pcol = (lane >> 4) << 3;
            #pragma unroll
            for (int kk = 0; kk < 4; kk++)
                ldsm4(pf[kk], &Ps[prow * kKS + kk * 16 + pcol]);
        }
        #pragma unroll
        for (int ch = 0; ch < 4; ch++) {
            int g = it * kChunksPerIter + 4 + ch;
            if (g + 1 < kTotalChunks) cpwait1(); else cpwait0();
            __syncthreads();
            if (gi < kTotalChunks) { issue_chunk(gi); gi++; }
            const __half* Vh = (const __half*)(smem + kOffStage + (g % 3) * kStageBytes);
            const __half* Vl = (const __half*)((const char*)Vh + kStageHalf);

            int brow = wn * 32 + (lane & 7) + ((lane >> 4) << 3);
            int bcol = ((lane >> 3) & 1) << 3;
            #pragma unroll
            for (int kk = 0; kk < 4; kk++) {
                #pragma unroll
                for (int t2 = 0; t2 < 2; t2++) {
                    u32 vh4[4], vl4[4];
                    ldsm4(vh4, &Vh[(brow + t2 * 16) * kKS + kk * 16 + bcol]);
                    ldsm4(vl4, &Vl[(brow + t2 * 16) * kKS + kk * 16 + bcol]);
                    mma16816(acc_o[ch][t2 * 2 + 0], pf[kk], vh4[0], vh4[1]);
                    mma16816(acc_o[ch][t2 * 2 + 0], pf[kk], vl4[0], vl4[1]);
                    mma16816(acc_o[ch][t2 * 2 + 1], pf[kk], vh4[2], vh4[3]);
                    mma16816(acc_o[ch][t2 * 2 + 1], pf[kk], vl4[2], vl4[3]);
                }
            }
        }
    }

    // ======== epilogue: normalize, blend, store ========
    __syncthreads();
    float gamma = gamma_p[0];
    float invA = 1.0f / rsum_s[rowA], invB = 1.0f / rsum_s[rowB];

    #pragma unroll
    for (int ch = 0; ch < 4; ch++) {
        __syncthreads();
        #pragma unroll
        for (int t = 0; t < 4; t++) {
            int c0 = wn * 32 + t * 8 + ((lane & 3) << 1);
            Osm[c0 * kOS + rowA]       = acc_o[ch][t][0] * invA;
            Osm[(c0 + 1) * kOS + rowA] = acc_o[ch][t][1] * invA;
            Osm[c0 * kOS + rowB]       = acc_o[ch][t][2] * invB;
            Osm[(c0 + 1) * kOS + rowB] = acc_o[ch][t][3] * invB;
        }
        __syncthreads();
        int r = tid >> 3, c4 = (tid & 7) << 4;
        size_t gb = ((size_t)bat * CDIM + ch * 64 + r) * HWDIM + i0 + c4;
        #pragma unroll
        for (int u = 0; u < 4; u++) {
            float4 o4 = *(float4*)&Osm[r * kOS + c4 + u * 4];
            float4 a4 = *(const float4*)&a_in[gb + u * 4];
            float ov[4] = {o4.x, o4.y, o4.z, o4.w};
            float av[4] = {a4.x, a4.y, a4.z, a4.w};
            float rr[4];
            #pragma unroll
            for (int e = 0; e < 4; e++) {
                float m = m_s[c4 + u * 4 + e];
                rr[e] = av[e] * m + gamma * (1.0f - m) * ov[e];
            }
            *(float4*)&out[gb + u * 4] = make_float4(rr[0], rr[1], rr[2], rr[3]);
        }
    }
}

// ---------------- launch ----------------
extern "C" void kernel_launch(void* const* d_in, const int* in_sizes, int n_in,
                              void* d_out, int out_size)
{
    const float* a  = (const float*)d_in[0];
    const float* b  = (const float*)d_in[1];
    const float* c  = (const float*)d_in[2];
    const float* wq = (const float*)d_in[3];
    const float* bq = (const float*)d_in[4];
    const float* gq = (const float*)d_in[5];
    const float* wk = (const float*)d_in[6];
    const float* bk = (const float*)d_in[7];
    const float* gk = (const float*)d_in[8];
    const float* wv = (const float*)d_in[9];
    const float* bv = (const float*)d_in[10];
    const float* gv = (const float*)d_in[11];
    const float* gm = (const float*)d_in[12];
    float* out = (float*)d_out;

    cudaFuncSetAttribute(attn_kernel, cudaFuncAttributeMaxDynamicSharedMemorySize, kSmemBytes);

    ws_kernel<<<CDIM, CDIM>>>(wq, gq, 0);
    ws_kernel<<<CDIM, CDIM>>>(wk, gk, 1);
    ws_kernel<<<CDIM, CDIM>>>(wv, gv, 2);

    dim3 g1(HWDIM / 64, CDIM / 64, 12);
    qkv_kernel<<<g1, 256>>>(a, b, bq, bk, bv);

    dim3 g2(HWDIM / kBM, BDIM);
    attn_kernel<<<g2, 512, kSmemBytes>>>(a, c, gm, out);
}

// round 9
// speedup vs baseline: 4.0970x; 1.1440x over previous
#include <cuda_runtime.h>
#include <cuda_fp16.h>
#include <cstdint>
#include <math.h>

typedef unsigned int u32;

#define CDIM  256
#define HWDIM 4096
#define BDIM  4

// ---------------- device scratch ----------------
__device__ __align__(16) __half g_wh[3][CDIM * CDIM];      // standardized W hi, [o][c]
__device__ __align__(16) __half g_wl[3][CDIM * CDIM];      // standardized W lo, [o][c]
__device__ __align__(16) __half g_qh[BDIM * HWDIM * CDIM]; // q hi  [b][i][c]
__device__ __align__(16) __half g_ql[BDIM * HWDIM * CDIM]; // q lo
__device__ __align__(16) __half g_kh[BDIM * HWDIM * CDIM]; // k hi  [b][j][c]
__device__ __align__(16) __half g_kl[BDIM * HWDIM * CDIM];
__device__ __align__(16) __half g_vh[BDIM * CDIM * HWDIM]; // v hi  [b][c][j]
__device__ __align__(16) __half g_vl[BDIM * CDIM * HWDIM];

// ---------------- mma / ldmatrix / cp.async helpers ----------------
__device__ __forceinline__ void ldsm4(u32* r, const void* p) {
    u32 addr = (u32)__cvta_generic_to_shared(p);
    asm volatile("ldmatrix.sync.aligned.m8n8.x4.shared.b16 {%0,%1,%2,%3}, [%4];"
                 : "=r"(r[0]), "=r"(r[1]), "=r"(r[2]), "=r"(r[3]) : "r"(addr));
}
__device__ __forceinline__ void ldsm4t(u32* r, const void* p) {
    u32 addr = (u32)__cvta_generic_to_shared(p);
    asm volatile("ldmatrix.sync.aligned.m8n8.x4.trans.shared.b16 {%0,%1,%2,%3}, [%4];"
                 : "=r"(r[0]), "=r"(r[1]), "=r"(r[2]), "=r"(r[3]) : "r"(addr));
}
__device__ __forceinline__ void mma16816(float* d, const u32* a, u32 b0, u32 b1) {
    asm volatile("mma.sync.aligned.m16n8k16.row.col.f32.f16.f16.f32 "
                 "{%0,%1,%2,%3}, {%4,%5,%6,%7}, {%8,%9}, {%0,%1,%2,%3};"
                 : "+f"(d[0]), "+f"(d[1]), "+f"(d[2]), "+f"(d[3])
                 : "r"(a[0]), "r"(a[1]), "r"(a[2]), "r"(a[3]), "r"(b0), "r"(b1));
}
__device__ __forceinline__ void cpasync16(u32 smem_dst, const void* gptr) {
    asm volatile("cp.async.cg.shared.global [%0], [%1], 16;" :: "r"(smem_dst), "l"(gptr));
}
__device__ __forceinline__ void cpcommit() { asm volatile("cp.async.commit_group;"); }
__device__ __forceinline__ void cpwait1()  { asm volatile("cp.async.wait_group 1;"); }
__device__ __forceinline__ void cpwait0()  { asm volatile("cp.async.wait_group 0;"); }

// ---------------- 1) weight standardization -> split fp16 [o][c] ----------------
__global__ void ws_kernel(const float* __restrict__ w,
                          const float* __restrict__ gain, int set)
{
    int o = blockIdx.x, c = threadIdx.x;
    float v = w[o * CDIM + c];
    float s = v, s2 = v * v;
    #pragma unroll
    for (int off = 16; off; off >>= 1) {
        s  += __shfl_xor_sync(0xffffffffu, s,  off);
        s2 += __shfl_xor_sync(0xffffffffu, s2, off);
    }
    __shared__ float red[16];
    int warp = c >> 5, lane = c & 31;
    if (lane == 0) { red[warp] = s; red[8 + warp] = s2; }
    __syncthreads();
    if (c == 0) {
        float ts = 0.f, ts2 = 0.f;
        #pragma unroll
        for (int i = 0; i < 8; i++) { ts += red[i]; ts2 += red[8 + i]; }
        red[0] = ts; red[8] = ts2;
    }
    __syncthreads();
    float mean = red[0] * (1.0f / CDIM);
    float var  = (red[8] - (float)CDIM * mean * mean) * (1.0f / (CDIM - 1));
    float scale = rsqrtf(fmaxf(var * (float)CDIM, 1e-4f)) * gain[o];
    float wsv = (v - mean) * scale;
    __half hh = __float2half_rn(wsv);
    __half ll = __float2half_rn(wsv - __half2float(hh));
    g_wh[set][o * CDIM + c] = hh;
    g_wl[set][o * CDIM + c] = ll;
}

// ---------------- 2) QKV GEMM on tensor cores (split fp16) ----------------
// out[o][i] = sum_c W[o][c] * X[c][i] + bias[o];  block = 128o x 128i, K-chunk 64
constexpr int kWS2 = 72;    // W smem stride (halves)
constexpr int kXS2 = 136;   // X smem stride (halves)
constexpr int kES2 = 136;   // epilogue stride (halves)
constexpr int kOffWl2 = 128 * kWS2 * 2;            // 18432
constexpr int kOffXh2 = 2 * kOffWl2;               // 36864
constexpr int kOffXl2 = kOffXh2 + 64 * kXS2 * 2;   // 54272
constexpr int kQkvSmem = kOffXl2 + 64 * kXS2 * 2;  // 71680
// epilogue aliases: hi at 0 (128*kES2*2 = 34816), lo at 34816 (total 69632 < 71680)

__global__ __launch_bounds__(256) void qkv_kernel(
    const float* __restrict__ a_in, const float* __restrict__ b_in,
    const float* __restrict__ bq, const float* __restrict__ bk, const float* __restrict__ bv)
{
    extern __shared__ char sm2[];
    __half* Wh = (__half*)sm2;
    __half* Wl = (__half*)(sm2 + kOffWl2);
    __half* Xh = (__half*)(sm2 + kOffXh2);
    __half* Xl = (__half*)(sm2 + kOffXl2);
    __half* Eh = (__half*)sm2;
    __half* El = (__half*)(sm2 + 34816);

    int set = blockIdx.z >> 2;
    int bat = blockIdx.z & 3;
    const float* X    = ((set == 1) ? b_in : a_in) + (size_t)bat * CDIM * HWDIM;
    const float* bias = (set == 0) ? bq : (set == 1) ? bk : bv;
    const __half* GW_h = g_wh[set];
    const __half* GW_l = g_wl[set];

    int i0 = blockIdx.x * 128, o0 = blockIdx.y * 128;
    int tid = threadIdx.x, lane = tid & 31, wid = tid >> 5;
    int wm = wid & 3, wn = wid >> 2;

    float acc[2][8][4];
    #pragma unroll
    for (int mi = 0; mi < 2; mi++)
        #pragma unroll
        for (int f = 0; f < 8; f++)
            #pragma unroll
            for (int e = 0; e < 4; e++) acc[mi][f][e] = 0.f;

    for (int k0 = 0; k0 < CDIM; k0 += 64) {
        __syncthreads();
        // W tiles (halves, raw copy)
        #pragma unroll
        for (int q = 0; q < 4; q++) {
            int f = tid + q * 256;
            int r = f >> 3, c8 = (f & 7) << 3;
            size_t gb = (size_t)(o0 + r) * CDIM + k0 + c8;
            *(float4*)&Wh[r * kWS2 + c8] = *(const float4*)&GW_h[gb];
            *(float4*)&Wl[r * kWS2 + c8] = *(const float4*)&GW_l[gb];
        }
        // X tile fp32 -> split halves, [k][n] layout
        #pragma unroll
        for (int q = 0; q < 8; q++) {
            int f = tid + q * 256;
            int r = f >> 5, c4 = (f & 31) << 2;
            float4 x4 = *(const float4*)&X[(size_t)(k0 + r) * HWDIM + i0 + c4];
            float xv[4] = {x4.x, x4.y, x4.z, x4.w};
            __half hs[4], ls[4];
            #pragma unroll
            for (int j = 0; j < 4; j++) {
                hs[j] = __float2half_rn(xv[j]);
                ls[j] = __float2half_rn(xv[j] - __half2float(hs[j]));
            }
            *(__half2*)&Xh[r * kXS2 + c4]     = __halves2half2(hs[0], hs[1]);
            *(__half2*)&Xh[r * kXS2 + c4 + 2] = __halves2half2(hs[2], hs[3]);
            *(__half2*)&Xl[r * kXS2 + c4]     = __halves2half2(ls[0], ls[1]);
            *(__half2*)&Xl[r * kXS2 + c4 + 2] = __halves2half2(ls[2], ls[3]);
        }
        __syncthreads();

        int arow0 = wm * 32 + (lane & 15);
        int acol  = (lane >> 4) << 3;
        int bk_r  = (lane & 7) + ((lane >> 3) & 1) * 8;   // k row within 16
        int bn_c  = ((lane >> 4) & 1) * 8;                // n col offset
        #pragma unroll
        for (int ks = 0; ks < 4; ks++) {
            u32 ah[2][4], al[2][4];
            #pragma unroll
            for (int mi = 0; mi < 2; mi++) {
                ldsm4(ah[mi], &Wh[(arow0 + mi * 16) * kWS2 + ks * 16 + acol]);
                ldsm4(al[mi], &Wl[(arow0 + mi * 16) * kWS2 + ks * 16 + acol]);
            }
            #pragma unroll
            for (int nb = 0; nb < 4; nb++) {
                int n0 = wn * 64 + nb * 16;
                u32 bh[4], bl[4];
                ldsm4t(bh, &Xh[(ks * 16 + bk_r) * kXS2 + n0 + bn_c]);
                ldsm4t(bl, &Xl[(ks * 16 + bk_r) * kXS2 + n0 + bn_c]);
                #pragma unroll
                for (int mi = 0; mi < 2; mi++) {
                    #pragma unroll
                    for (int s = 0; s < 2; s++) {
                        float* d = acc[mi][nb * 2 + s];
                        mma16816(d, ah[mi], bh[s * 2], bh[s * 2 + 1]);
                        mma16816(d, ah[mi], bl[s * 2], bl[s * 2 + 1]);
                        mma16816(d, al[mi], bh[s * 2], bh[s * 2 + 1]);
                    }
                }
            }
        }
    }
    __syncthreads();

    // ---- epilogue: add bias, split to hi/lo, stage, coalesced store ----
    // q/k: stage [i][o]; v: stage [o][i]
    #pragma unroll
    for (int mi = 0; mi < 2; mi++) {
        #pragma unroll
        for (int p = 0; p < 2; p++) {
            int r = wm * 32 + mi * 16 + (lane >> 2) + p * 8;   // local o
            float bb = bias[o0 + r];
            #pragma unroll
            for (int f = 0; f < 8; f++) {
                int cbase = wn * 64 + (f >> 1) * 16 + (f & 1) * 8 + ((lane & 3) << 1);  // local i
                #pragma unroll
                for (int e = 0; e < 2; e++) {
                    float x = acc[mi][f][p * 2 + e] + bb;
                    __half hh = __float2half_rn(x);
                    __half ll = __float2half_rn(x - __half2float(hh));
                    if (set == 2) {
                        Eh[r * kES2 + cbase + e] = hh;
                        El[r * kES2 + cbase + e] = ll;
                    } else {
                        Eh[(cbase + e) * kES2 + r] = hh;
                        El[(cbase + e) * kES2 + r] = ll;
                    }
                }
            }
        }
    }
    __syncthreads();

    __half* OH; __half* OL; size_t rbase; size_t rstride;
    if (set == 2) {
        OH = g_vh; OL = g_vl;
        rbase = ((size_t)bat * CDIM + o0) * HWDIM + i0;
        rstride = HWDIM;
    } else {
        OH = set ? g_kh : g_qh;
        OL = set ? g_kl : g_ql;
        rbase = ((size_t)bat * HWDIM + i0) * CDIM + o0;
        rstride = CDIM;
    }
    #pragma unroll
    for (int q = 0; q < 8; q++) {
        int f = tid + q * 256;
        int r = f >> 4, c8 = (f & 15) << 3;
        *(float4*)&OH[rbase + (size_t)r * rstride + c8] = *(float4*)&Eh[r * kES2 + c8];
        *(float4*)&OL[rbase + (size_t)r * rstride + c8] = *(float4*)&El[r * kES2 + c8];
    }
}

// ---------------- 3) flash attention, BM=128, cp.async 3-stage pipeline ----------------
constexpr int kBM  = 128;
constexpr int kQS  = 264;
constexpr int kKS  = 72;
constexpr int kOS  = 132;
constexpr int kQhBytes    = kBM * kQS * 2;
constexpr int kOffQl      = kQhBytes;
constexpr int kStageHalf  = 64 * kKS * 2;
constexpr int kStageBytes = 2 * kStageHalf;
constexpr int kOffStage   = 2 * kQhBytes;
constexpr int kOffPs      = kOffStage + 3 * kStageBytes;
constexpr int kOffF32     = kOffPs + kBM * kKS * 2;
constexpr int kSmemBytes  = kOffF32 + 4096;
constexpr int kChunksPerIter = 8;
constexpr int kTotalChunks   = (HWDIM / 64) * kChunksPerIter;

__global__ __launch_bounds__(512) void attn_kernel(
    const float* __restrict__ a_in, const float* __restrict__ cm,
    const float* __restrict__ gamma_p, float* __restrict__ out)
{
    extern __shared__ char smem[];
    __half* Qh = (__half*)smem;
    __half* Ql = (__half*)(smem + kOffQl);
    __half* Ps = (__half*)(smem + kOffPs);
    float*  m_s     = (float*)(smem + kOffF32);
    float*  rmax_s  = m_s + 128;
    float*  rsum_s  = m_s + 256;
    float*  alpha_s = m_s + 384;
    float*  maxbuf  = m_s + 512;
    float*  sumbuf  = m_s + 768;
    float*  Osm     = (float*)smem;

    int bat = blockIdx.y;
    int i0  = blockIdx.x * kBM;
    int tid = threadIdx.x, lane = tid & 31, wid = tid >> 5;
    int wm = wid & 7, wn = wid >> 3;

    const __half* GQh = g_qh + (size_t)bat * HWDIM * CDIM;
    const __half* GQl = g_ql + (size_t)bat * HWDIM * CDIM;
    const __half* GKh = g_kh + (size_t)bat * HWDIM * CDIM;
    const __half* GKl = g_kl + (size_t)bat * HWDIM * CDIM;
    const __half* GVh = g_vh + (size_t)bat * CDIM * HWDIM;
    const __half* GVl = g_vl + (size_t)bat * CDIM * HWDIM;

    int cr = tid >> 3, cc8 = (tid & 7) << 3;
    auto issue_chunk = [&](int g) {
        int itj = g >> 3, c = g & 7;
        int j0 = itj * 64;
        const __half *srcH, *srcL;
        if (c < 4) {
            size_t o = (size_t)(j0 + cr) * CDIM + c * 64 + cc8;
            srcH = GKh + o; srcL = GKl + o;
        } else {
            size_t o = (size_t)((c - 4) * 64 + cr) * HWDIM + j0 + cc8;
            srcH = GVh + o; srcL = GVl + o;
        }
        u32 dH = (u32)__cvta_generic_to_shared(smem + kOffStage + (g % 3) * kStageBytes
                                               + (cr * kKS + cc8) * 2);
        cpasync16(dH, srcH);
        cpasync16(dH + kStageHalf, srcL);
        cpcommit();
    };

    issue_chunk(0);
    issue_chunk(1);
    int gi = 2;

    if (tid < kBM) {
        int i = i0 + tid;
        m_s[tid] = cm[bat * 1024 + ((i >> 6) >> 1) * 32 + ((i & 63) >> 1)];
        rmax_s[tid] = -INFINITY;
        rsum_s[tid] = 0.f;
    }
    #pragma unroll
    for (int t = 0; t < 8; t++) {
        int idx = tid + t * 512;
        int r = idx >> 5, c8 = (idx & 31) << 3;
        size_t gb = (size_t)(i0 + r) * CDIM + c8;
        *(float4*)&Qh[r * kQS + c8] = *(const float4*)&GQh[gb];
        *(float4*)&Ql[r * kQS + c8] = *(const float4*)&GQl[gb];
    }
    __syncthreads();

    int rowA = wm * 16 + (lane >> 2), rowB = rowA + 8;
    float mA = m_s[rowA], mB = m_s[rowB];

    float acc_o[4][4][4];
    #pragma unroll
    for (int c = 0; c < 4; c++)
        #pragma unroll
        for (int t = 0; t < 4; t++)
            #pragma unroll
            for (int e = 0; e < 4; e++) acc_o[c][t][e] = 0.f;

    for (int it = 0; it < HWDIM / 64; it++) {
        float sacc[4][4];
        #pragma unroll
        for (int t = 0; t < 4; t++)
            #pragma unroll
            for (int e = 0; e < 4; e++) sacc[t][e] = 0.f;

        #pragma unroll
        for (int ch = 0; ch < 4; ch++) {
            int g = it * kChunksPerIter + ch;
            cpwait1();
            __syncthreads();
            if (gi < kTotalChunks) { issue_chunk(gi); gi++; }
            const __half* Kh = (const __half*)(smem + kOffStage + (g % 3) * kStageBytes);
            const __half* Kl = (const __half*)((const char*)Kh + kStageHalf);

            int arow = wm * 16 + (lane & 15);
            int acol = ch * 64 + ((lane >> 4) << 3);
            int brow = wn * 32 + (lane & 7) + ((lane >> 4) << 3);
            int bcol = ((lane >> 3) & 1) << 3;
            #pragma unroll
            for (int kk = 0; kk < 4; kk++) {
                u32 qa[4], qb[4];
                ldsm4(qa, &Qh[arow * kQS + acol + kk * 16]);
                ldsm4(qb, &Ql[arow * kQS + acol + kk * 16]);
                #pragma unroll
                for (int t2 = 0; t2 < 2; t2++) {
                    u32 kh4[4], kl4[4];
                    ldsm4(kh4, &Kh[(brow + t2 * 16) * kKS + kk * 16 + bcol]);
                    ldsm4(kl4, &Kl[(brow + t2 * 16) * kKS + kk * 16 + bcol]);
                    mma16816(sacc[t2 * 2 + 0], qa, kh4[0], kh4[1]);
                    mma16816(sacc[t2 * 2 + 0], qa, kl4[0], kl4[1]);
                    mma16816(sacc[t2 * 2 + 0], qb, kh4[0], kh4[1]);
                    mma16816(sacc[t2 * 2 + 1], qa, kh4[2], kh4[3]);
                    mma16816(sacc[t2 * 2 + 1], qa, kl4[2], kl4[3]);
                    mma16816(sacc[t2 * 2 + 1], qb, kh4[2], kh4[3]);
                }
            }
        }

        float vmaxA = -INFINITY, vmaxB = -INFINITY;
        #pragma unroll
        for (int t = 0; t < 4; t++) {
            sacc[t][0] *= mA; sacc[t][1] *= mA;
            sacc[t][2] *= mB; sacc[t][3] *= mB;
            vmaxA = fmaxf(vmaxA, fmaxf(sacc[t][0], sacc[t][1]));
            vmaxB = fmaxf(vmaxB, fmaxf(sacc[t][2], sacc[t][3]));
        }
        #pragma unroll
        for (int off = 1; off < 4; off <<= 1) {
            vmaxA = fmaxf(vmaxA, __shfl_xor_sync(0xffffffffu, vmaxA, off));
            vmaxB = fmaxf(vmaxB, __shfl_xor_sync(0xffffffffu, vmaxB, off));
        }
        if ((lane & 3) == 0) {
            maxbuf[wn * 128 + rowA] = vmaxA;
            maxbuf[wn * 128 + rowB] = vmaxB;
        }
        __syncthreads();
        if (tid < kBM) {
            float nm = fmaxf(rmax_s[tid], fmaxf(maxbuf[tid], maxbuf[128 + tid]));
            alpha_s[tid] = __expf(rmax_s[tid] - nm);
            rmax_s[tid] = nm;
        }
        __syncthreads();
        float nmA = rmax_s[rowA], nmB = rmax_s[rowB];
        float alA = alpha_s[rowA], alB = alpha_s[rowB];
        float psA = 0.f, psB = 0.f;
        #pragma unroll
        for (int t = 0; t < 4; t++) {
            float p0 = __expf(sacc[t][0] - nmA), p1 = __expf(sacc[t][1] - nmA);
            float p2 = __expf(sacc[t][2] - nmB), p3 = __expf(sacc[t][3] - nmB);
            psA += p0 + p1; psB += p2 + p3;
            int col = wn * 32 + t * 8 + ((lane & 3) << 1);
            *(__half2*)&Ps[rowA * kKS + col] = __floats2half2_rn(p0, p1);
            *(__half2*)&Ps[rowB * kKS + col] = __floats2half2_rn(p2, p3);
        }
        #pragma unroll
        for (int c = 0; c < 4; c++)
            #pragma unroll
            for (int t = 0; t < 4; t++) {
                acc_o[c][t][0] *= alA; acc_o[c][t][1] *= alA;
                acc_o[c][t][2] *= alB; acc_o[c][t][3] *= alB;
            }
        #pragma unroll
        for (int off = 1; off < 4; off <<= 1) {
            psA += __shfl_xor_sync(0xffffffffu, psA, off);
            psB += __shfl_xor_sync(0xffffffffu, psB, off);
        }
        if ((lane & 3) == 0) {
            sumbuf[wn * 128 + rowA] = psA;
            sumbuf[wn * 128 + rowB] = psB;
        }
        __syncthreads();
        if (tid < kBM)
            rsum_s[tid] = rsum_s[tid] * alpha_s[tid] + sumbuf[tid] + sumbuf[128 + tid];

        u32 pf[4][4];
        {
            int prow = wm * 16 + (lane & 15);
            int pcol = (lane >> 4) << 3;
            #pragma unroll
            for (int kk = 0; kk < 4; kk++)
                ldsm4(pf[kk], &Ps[prow * kKS + kk * 16 + pcol]);
        }
        #pragma unroll
        for (int ch = 0; ch < 4; ch++) {
            int g = it * kChunksPerIter + 4 + ch;
            if (g + 1 < kTotalChunks) cpwait1(); else cpwait0();
            __syncthreads();
            if (gi < kTotalChunks) { issue_chunk(gi); gi++; }
            const __half* Vh = (const __half*)(smem + kOffStage + (g % 3) * kStageBytes);
            const __half* Vl = (const __half*)((const char*)Vh + kStageHalf);

            int brow = wn * 32 + (lane & 7) + ((lane >> 4) << 3);
            int bcol = ((lane >> 3) & 1) << 3;
            #pragma unroll
            for (int kk = 0; kk < 4; kk++) {
                #pragma unroll
                for (int t2 = 0; t2 < 2; t2++) {
                    u32 vh4[4], vl4[4];
                    ldsm4(vh4, &Vh[(brow + t2 * 16) * kKS + kk * 16 + bcol]);
                    ldsm4(vl4, &Vl[(brow + t2 * 16) * kKS + kk * 16 + bcol]);
                    mma16816(acc_o[ch][t2 * 2 + 0], pf[kk], vh4[0], vh4[1]);
                    mma16816(acc_o[ch][t2 * 2 + 0], pf[kk], vl4[0], vl4[1]);
                    mma16816(acc_o[ch][t2 * 2 + 1], pf[kk], vh4[2], vh4[3]);
                    mma16816(acc_o[ch][t2 * 2 + 1], pf[kk], vl4[2], vl4[3]);
                }
            }
        }
    }

    __syncthreads();
    float gamma = gamma_p[0];
    float invA = 1.0f / rsum_s[rowA], invB = 1.0f / rsum_s[rowB];

    #pragma unroll
    for (int ch = 0; ch < 4; ch++) {
        __syncthreads();
        #pragma unroll
        for (int t = 0; t < 4; t++) {
            int c0 = wn * 32 + t * 8 + ((lane & 3) << 1);
            Osm[c0 * kOS + rowA]       = acc_o[ch][t][0] * invA;
            Osm[(c0 + 1) * kOS + rowA] = acc_o[ch][t][1] * invA;
            Osm[c0 * kOS + rowB]       = acc_o[ch][t][2] * invB;
            Osm[(c0 + 1) * kOS + rowB] = acc_o[ch][t][3] * invB;
        }
        __syncthreads();
        int r = tid >> 3, c4 = (tid & 7) << 4;
        size_t gb = ((size_t)bat * CDIM + ch * 64 + r) * HWDIM + i0 + c4;
        #pragma unroll
        for (int u = 0; u < 4; u++) {
            float4 o4 = *(float4*)&Osm[r * kOS + c4 + u * 4];
            float4 a4 = *(const float4*)&a_in[gb + u * 4];
            float ov[4] = {o4.x, o4.y, o4.z, o4.w};
            float av[4] = {a4.x, a4.y, a4.z, a4.w};
            float rr[4];
            #pragma unroll
            for (int e = 0; e < 4; e++) {
                float m = m_s[c4 + u * 4 + e];
                rr[e] = av[e] * m + gamma * (1.0f - m) * ov[e];
            }
            *(float4*)&out[gb + u * 4] = make_float4(rr[0], rr[1], rr[2], rr[3]);
        }
    }
}

// ---------------- launch ----------------
extern "C" void kernel_launch(void* const* d_in, const int* in_sizes, int n_in,
                              void* d_out, int out_size)
{
    const float* a  = (const float*)d_in[0];
    const float* b  = (const float*)d_in[1];
    const float* c  = (const float*)d_in[2];
    const float* wq = (const float*)d_in[3];
    const float* bq = (const float*)d_in[4];
    const float* gq = (const float*)d_in[5];
    const float* wk = (const float*)d_in[6];
    const float* bk = (const float*)d_in[7];
    const float* gk = (const float*)d_in[8];
    const float* wv = (const float*)d_in[9];
    const float* bv = (const float*)d_in[10];
    const float* gv = (const float*)d_in[11];
    const float* gm = (const float*)d_in[12];
    float* out = (float*)d_out;

    cudaFuncSetAttribute(qkv_kernel, cudaFuncAttributeMaxDynamicSharedMemorySize, kQkvSmem);
    cudaFuncSetAttribute(attn_kernel, cudaFuncAttributeMaxDynamicSharedMemorySize, kSmemBytes);

    ws_kernel<<<CDIM, CDIM>>>(wq, gq, 0);
    ws_kernel<<<CDIM, CDIM>>>(wk, gk, 1);
    ws_kernel<<<CDIM, CDIM>>>(wv, gv, 2);

    dim3 g1(HWDIM / 128, CDIM / 128, 12);
    qkv_kernel<<<g1, 256, kQkvSmem>>>(a, b, bq, bk, bv);

    dim3 g2(HWDIM / kBM, BDIM);
    attn_kernel<<<g2, 512, kSmemBytes>>>(a, c, gm, out);
}

// round 10
// speedup vs baseline: 4.9049x; 1.1972x over previous
#include <cuda_runtime.h>
#include <cuda_fp16.h>
#include <cstdint>
#include <math.h>

typedef unsigned int u32;

#define CDIM  256
#define HWDIM 4096
#define BDIM  4

// ---------------- device scratch ----------------
__device__ __align__(16) __half g_wh[3][CDIM * CDIM];      // standardized W hi, [o][c]
__device__ __align__(16) __half g_wl[3][CDIM * CDIM];      // standardized W lo, [o][c]
__device__ __align__(16) __half g_qh[BDIM * HWDIM * CDIM]; // q hi  [b][i][c]
__device__ __align__(16) __half g_ql[BDIM * HWDIM * CDIM]; // q lo
__device__ __align__(16) __half g_kh[BDIM * HWDIM * CDIM]; // k hi  [b][j][c]
__device__ __align__(16) __half g_kl[BDIM * HWDIM * CDIM];
__device__ __align__(16) __half g_vh[BDIM * CDIM * HWDIM]; // v fp16 [b][c][j]

// ---------------- mma / ldmatrix / cp.async helpers ----------------
__device__ __forceinline__ void ldsm4(u32* r, const void* p) {
    u32 addr = (u32)__cvta_generic_to_shared(p);
    asm volatile("ldmatrix.sync.aligned.m8n8.x4.shared.b16 {%0,%1,%2,%3}, [%4];"
                 : "=r"(r[0]), "=r"(r[1]), "=r"(r[2]), "=r"(r[3]) : "r"(addr));
}
__device__ __forceinline__ void ldsm4t(u32* r, const void* p) {
    u32 addr = (u32)__cvta_generic_to_shared(p);
    asm volatile("ldmatrix.sync.aligned.m8n8.x4.trans.shared.b16 {%0,%1,%2,%3}, [%4];"
                 : "=r"(r[0]), "=r"(r[1]), "=r"(r[2]), "=r"(r[3]) : "r"(addr));
}
__device__ __forceinline__ void mma16816(float* d, const u32* a, u32 b0, u32 b1) {
    asm volatile("mma.sync.aligned.m16n8k16.row.col.f32.f16.f16.f32 "
                 "{%0,%1,%2,%3}, {%4,%5,%6,%7}, {%8,%9}, {%0,%1,%2,%3};"
                 : "+f"(d[0]), "+f"(d[1]), "+f"(d[2]), "+f"(d[3])
                 : "r"(a[0]), "r"(a[1]), "r"(a[2]), "r"(a[3]), "r"(b0), "r"(b1));
}
__device__ __forceinline__ void cpasync16(u32 smem_dst, const void* gptr) {
    asm volatile("cp.async.cg.shared.global [%0], [%1], 16;" :: "r"(smem_dst), "l"(gptr));
}
__device__ __forceinline__ void cpcommit() { asm volatile("cp.async.commit_group;"); }
__device__ __forceinline__ void cpwait1()  { asm volatile("cp.async.wait_group 1;"); }
__device__ __forceinline__ void cpwait0()  { asm volatile("cp.async.wait_group 0;"); }
__device__ __forceinline__ void barpair(int id) {
    asm volatile("bar.sync %0, %1;" :: "r"(id), "r"(64) : "memory");
}

// ---------------- 1) weight standardization -> split fp16 [o][c] ----------------
__global__ void ws_kernel(const float* __restrict__ w,
                          const float* __restrict__ gain, int set)
{
    int o = blockIdx.x, c = threadIdx.x;
    float v = w[o * CDIM + c];
    float s = v, s2 = v * v;
    #pragma unroll
    for (int off = 16; off; off >>= 1) {
        s  += __shfl_xor_sync(0xffffffffu, s,  off);
        s2 += __shfl_xor_sync(0xffffffffu, s2, off);
    }
    __shared__ float red[16];
    int warp = c >> 5, lane = c & 31;
    if (lane == 0) { red[warp] = s; red[8 + warp] = s2; }
    __syncthreads();
    if (c == 0) {
        float ts = 0.f, ts2 = 0.f;
        #pragma unroll
        for (int i = 0; i < 8; i++) { ts += red[i]; ts2 += red[8 + i]; }
        red[0] = ts; red[8] = ts2;
    }
    __syncthreads();
    float mean = red[0] * (1.0f / CDIM);
    float var  = (red[8] - (float)CDIM * mean * mean) * (1.0f / (CDIM - 1));
    float scale = rsqrtf(fmaxf(var * (float)CDIM, 1e-4f)) * gain[o];
    float wsv = (v - mean) * scale;
    __half hh = __float2half_rn(wsv);
    __half ll = __float2half_rn(wsv - __half2float(hh));
    g_wh[set][o * CDIM + c] = hh;
    g_wl[set][o * CDIM + c] = ll;
}

// ---------------- 2) QKV GEMM on tensor cores (split fp16) ----------------
constexpr int kWS2 = 72;    // W smem stride (halves)
constexpr int kXS2 = 136;   // X smem stride (halves)
constexpr int kES2 = 136;   // epilogue stride (halves)
constexpr int kOffWl2 = 128 * kWS2 * 2;            // 18432
constexpr int kOffXh2 = 2 * kOffWl2;               // 36864
constexpr int kOffXl2 = kOffXh2 + 64 * kXS2 * 2;   // 54272
constexpr int kQkvSmem = kOffXl2 + 64 * kXS2 * 2;  // 71680

__global__ __launch_bounds__(256, 2) void qkv_kernel(
    const float* __restrict__ a_in, const float* __restrict__ b_in,
    const float* __restrict__ bq, const float* __restrict__ bk, const float* __restrict__ bv)
{
    extern __shared__ char sm2[];
    __half* Wh = (__half*)sm2;
    __half* Wl = (__half*)(sm2 + kOffWl2);
    __half* Xh = (__half*)(sm2 + kOffXh2);
    __half* Xl = (__half*)(sm2 + kOffXl2);
    __half* Eh = (__half*)sm2;
    __half* El = (__half*)(sm2 + 34816);

    int set = blockIdx.z >> 2;
    int bat = blockIdx.z & 3;
    const float* X    = ((set == 1) ? b_in : a_in) + (size_t)bat * CDIM * HWDIM;
    const float* bias = (set == 0) ? bq : (set == 1) ? bk : bv;
    const __half* GW_h = g_wh[set];
    const __half* GW_l = g_wl[set];

    int i0 = blockIdx.x * 128, o0 = blockIdx.y * 128;
    int tid = threadIdx.x, lane = tid & 31, wid = tid >> 5;
    int wm = wid & 3, wn = wid >> 2;

    float acc[2][8][4];
    #pragma unroll
    for (int mi = 0; mi < 2; mi++)
        #pragma unroll
        for (int f = 0; f < 8; f++)
            #pragma unroll
            for (int e = 0; e < 4; e++) acc[mi][f][e] = 0.f;

    for (int k0 = 0; k0 < CDIM; k0 += 64) {
        __syncthreads();
        #pragma unroll
        for (int q = 0; q < 4; q++) {
            int f = tid + q * 256;
            int r = f >> 3, c8 = (f & 7) << 3;
            size_t gb = (size_t)(o0 + r) * CDIM + k0 + c8;
            *(float4*)&Wh[r * kWS2 + c8] = *(const float4*)&GW_h[gb];
            *(float4*)&Wl[r * kWS2 + c8] = *(const float4*)&GW_l[gb];
        }
        #pragma unroll
        for (int q = 0; q < 8; q++) {
            int f = tid + q * 256;
            int r = f >> 5, c4 = (f & 31) << 2;
            float4 x4 = *(const float4*)&X[(size_t)(k0 + r) * HWDIM + i0 + c4];
            float xv[4] = {x4.x, x4.y, x4.z, x4.w};
            __half hs[4], ls[4];
            #pragma unroll
            for (int j = 0; j < 4; j++) {
                hs[j] = __float2half_rn(xv[j]);
                ls[j] = __float2half_rn(xv[j] - __half2float(hs[j]));
            }
            *(__half2*)&Xh[r * kXS2 + c4]     = __halves2half2(hs[0], hs[1]);
            *(__half2*)&Xh[r * kXS2 + c4 + 2] = __halves2half2(hs[2], hs[3]);
            *(__half2*)&Xl[r * kXS2 + c4]     = __halves2half2(ls[0], ls[1]);
            *(__half2*)&Xl[r * kXS2 + c4 + 2] = __halves2half2(ls[2], ls[3]);
        }
        __syncthreads();

        int arow0 = wm * 32 + (lane & 15);
        int acol  = (lane >> 4) << 3;
        int bk_r  = (lane & 7) + ((lane >> 3) & 1) * 8;
        int bn_c  = ((lane >> 4) & 1) * 8;
        #pragma unroll
        for (int ks = 0; ks < 4; ks++) {
            u32 ah[2][4], al[2][4];
            #pragma unroll
            for (int mi = 0; mi < 2; mi++) {
                ldsm4(ah[mi], &Wh[(arow0 + mi * 16) * kWS2 + ks * 16 + acol]);
                ldsm4(al[mi], &Wl[(arow0 + mi * 16) * kWS2 + ks * 16 + acol]);
            }
            #pragma unroll
            for (int nb = 0; nb < 4; nb++) {
                int n0 = wn * 64 + nb * 16;
                u32 bh[4], bl[4];
                ldsm4t(bh, &Xh[(ks * 16 + bk_r) * kXS2 + n0 + bn_c]);
                ldsm4t(bl, &Xl[(ks * 16 + bk_r) * kXS2 + n0 + bn_c]);
                #pragma unroll
                for (int mi = 0; mi < 2; mi++) {
                    #pragma unroll
                    for (int s = 0; s < 2; s++) {
                        float* d = acc[mi][nb * 2 + s];
                        mma16816(d, ah[mi], bh[s * 2], bh[s * 2 + 1]);
                        mma16816(d, ah[mi], bl[s * 2], bl[s * 2 + 1]);
                        mma16816(d, al[mi], bh[s * 2], bh[s * 2 + 1]);
                    }
                }
            }
        }
    }
    __syncthreads();

    // ---- epilogue: add bias, split to hi/lo, stage, coalesced store ----
    #pragma unroll
    for (int mi = 0; mi < 2; mi++) {
        #pragma unroll
        for (int p = 0; p < 2; p++) {
            int r = wm * 32 + mi * 16 + (lane >> 2) + p * 8;
            float bb = bias[o0 + r];
            #pragma unroll
            for (int f = 0; f < 8; f++) {
                int cbase = wn * 64 + (f >> 1) * 16 + (f & 1) * 8 + ((lane & 3) << 1);
                #pragma unroll
                for (int e = 0; e < 2; e++) {
                    float x = acc[mi][f][p * 2 + e] + bb;
                    __half hh = __float2half_rn(x);
                    __half ll = __float2half_rn(x - __half2float(hh));
                    if (set == 2) {
                        Eh[r * kES2 + cbase + e] = hh;
                        El[r * kES2 + cbase + e] = ll;
                    } else {
                        Eh[(cbase + e) * kES2 + r] = hh;
                        El[(cbase + e) * kES2 + r] = ll;
                    }
                }
            }
        }
    }
    __syncthreads();

    __half* OH; __half* OL; size_t rbase; size_t rstride;
    if (set == 2) {
        OH = g_vh; OL = g_vh;   // OL unused for set 2
        rbase = ((size_t)bat * CDIM + o0) * HWDIM + i0;
        rstride = HWDIM;
    } else {
        OH = set ? g_kh : g_qh;
        OL = set ? g_kl : g_ql;
        rbase = ((size_t)bat * HWDIM + i0) * CDIM + o0;
        rstride = CDIM;
    }
    #pragma unroll
    for (int q = 0; q < 8; q++) {
        int f = tid + q * 256;
        int r = f >> 4, c8 = (f & 15) << 3;
        *(float4*)&OH[rbase + (size_t)r * rstride + c8] = *(float4*)&Eh[r * kES2 + c8];
        if (set != 2)
            *(float4*)&OL[rbase + (size_t)r * rstride + c8] = *(float4*)&El[r * kES2 + c8];
    }
}

// ---------------- 3) flash attention, BM=128, 6-chunk/iter cp.async pipeline ----------------
constexpr int kBM  = 128;
constexpr int kQS  = 264;
constexpr int kKS  = 72;
constexpr int kOS  = 132;
constexpr int kQhBytes    = kBM * kQS * 2;
constexpr int kOffQl      = kQhBytes;
constexpr int kStageHalf  = 64 * kKS * 2;            // 9216
constexpr int kStageBytes = 2 * kStageHalf;          // 18432
constexpr int kOffStage   = 2 * kQhBytes;
constexpr int kOffPs      = kOffStage + 3 * kStageBytes;
constexpr int kOffF32     = kOffPs + kBM * kKS * 2;
constexpr int kSmemBytes  = kOffF32 + 4096;
constexpr int kChunksPerIter = 6;                    // K0..K3, Vpair0, Vpair1
constexpr int kTotalChunks   = (HWDIM / 64) * kChunksPerIter;  // 384

__global__ __launch_bounds__(512) void attn_kernel(
    const float* __restrict__ a_in, const float* __restrict__ cm,
    const float* __restrict__ gamma_p, float* __restrict__ out)
{
    extern __shared__ char smem[];
    __half* Qh = (__half*)smem;
    __half* Ql = (__half*)(smem + kOffQl);
    __half* Ps = (__half*)(smem + kOffPs);
    float*  m_s    = (float*)(smem + kOffF32);
    float*  maxbuf = m_s + 128;   // [2][128]
    float*  sumbuf = m_s + 384;   // [2][128]
    float*  Osm    = (float*)smem;

    int bat = blockIdx.y;
    int i0  = blockIdx.x * kBM;
    int tid = threadIdx.x, lane = tid & 31, wid = tid >> 5;
    int wm = wid & 7, wn = wid >> 3;

    const __half* GQh = g_qh + (size_t)bat * HWDIM * CDIM;
    const __half* GQl = g_ql + (size_t)bat * HWDIM * CDIM;
    const __half* GKh = g_kh + (size_t)bat * HWDIM * CDIM;
    const __half* GKl = g_kl + (size_t)bat * HWDIM * CDIM;
    const __half* GVh = g_vh + (size_t)bat * CDIM * HWDIM;

    int cr = tid >> 3, cc8 = (tid & 7) << 3;
    auto issue_chunk = [&](int g) {
        int itj = g / kChunksPerIter, c = g % kChunksPerIter;
        int j0 = itj * 64;
        u32 dH = (u32)__cvta_generic_to_shared(smem + kOffStage + (g % 3) * kStageBytes
                                               + (cr * kKS + cc8) * 2);
        if (c < 4) {
            size_t o = (size_t)(j0 + cr) * CDIM + c * 64 + cc8;
            cpasync16(dH, GKh + o);
            cpasync16(dH + kStageHalf, GKl + o);
        } else {
            int cpair = c - 4;
            size_t o0 = (size_t)(cpair * 128 + cr) * HWDIM + j0 + cc8;
            cpasync16(dH, GVh + o0);
            cpasync16(dH + kStageHalf, GVh + o0 + (size_t)64 * HWDIM);
        }
        cpcommit();
    };

    issue_chunk(0);
    issue_chunk(1);
    int gi = 2;

    if (tid < kBM) {
        int i = i0 + tid;
        m_s[tid] = cm[bat * 1024 + ((i >> 6) >> 1) * 32 + ((i & 63) >> 1)];
    }
    #pragma unroll
    for (int t = 0; t < 8; t++) {
        int idx = tid + t * 512;
        int r = idx >> 5, c8 = (idx & 31) << 3;
        size_t gb = (size_t)(i0 + r) * CDIM + c8;
        *(float4*)&Qh[r * kQS + c8] = *(const float4*)&GQh[gb];
        *(float4*)&Ql[r * kQS + c8] = *(const float4*)&GQl[gb];
    }
    __syncthreads();

    int rowA = wm * 16 + (lane >> 2), rowB = rowA + 8;
    float mA = m_s[rowA], mB = m_s[rowB];
    float rmaxA = -INFINITY, rmaxB = -INFINITY;
    float rsumA = 0.f, rsumB = 0.f;

    float acc_o[4][4][4];
    #pragma unroll
    for (int c = 0; c < 4; c++)
        #pragma unroll
        for (int t = 0; t < 4; t++)
            #pragma unroll
            for (int e = 0; e < 4; e++) acc_o[c][t][e] = 0.f;

    for (int it = 0; it < HWDIM / 64; it++) {
        // ======== S = Q^T K (split fp16, 3 mmas) ========
        float sacc[4][4];
        #pragma unroll
        for (int t = 0; t < 4; t++)
            #pragma unroll
            for (int e = 0; e < 4; e++) sacc[t][e] = 0.f;

        #pragma unroll
        for (int ch = 0; ch < 4; ch++) {
            int g = it * kChunksPerIter + ch;
            cpwait1();
            __syncthreads();
            if (gi < kTotalChunks) { issue_chunk(gi); gi++; }
            const __half* Kh = (const __half*)(smem + kOffStage + (g % 3) * kStageBytes);
            const __half* Kl = (const __half*)((const char*)Kh + kStageHalf);

            int arow = wm * 16 + (lane & 15);
            int acol = ch * 64 + ((lane >> 4) << 3);
            int brow = wn * 32 + (lane & 7) + ((lane >> 4) << 3);
            int bcol = ((lane >> 3) & 1) << 3;
            #pragma unroll
            for (int kk = 0; kk < 4; kk++) {
                u32 qa[4], qb[4];
                ldsm4(qa, &Qh[arow * kQS + acol + kk * 16]);
                ldsm4(qb, &Ql[arow * kQS + acol + kk * 16]);
                #pragma unroll
                for (int t2 = 0; t2 < 2; t2++) {
                    u32 kh4[4], kl4[4];
                    ldsm4(kh4, &Kh[(brow + t2 * 16) * kKS + kk * 16 + bcol]);
                    ldsm4(kl4, &Kl[(brow + t2 * 16) * kKS + kk * 16 + bcol]);
                    mma16816(sacc[t2 * 2 + 0], qa, kh4[0], kh4[1]);
                    mma16816(sacc[t2 * 2 + 0], qa, kl4[0], kl4[1]);
                    mma16816(sacc[t2 * 2 + 0], qb, kh4[0], kh4[1]);
                    mma16816(sacc[t2 * 2 + 1], qa, kh4[2], kh4[3]);
                    mma16816(sacc[t2 * 2 + 1], qa, kl4[2], kl4[3]);
                    mma16816(sacc[t2 * 2 + 1], qb, kh4[2], kh4[3]);
                }
            }
        }

        // ======== online softmax: pair-local (named barriers) ========
        float vmaxA = -INFINITY, vmaxB = -INFINITY;
        #pragma unroll
        for (int t = 0; t < 4; t++) {
            sacc[t][0] *= mA; sacc[t][1] *= mA;
            sacc[t][2] *= mB; sacc[t][3] *= mB;
            vmaxA = fmaxf(vmaxA, fmaxf(sacc[t][0], sacc[t][1]));
            vmaxB = fmaxf(vmaxB, fmaxf(sacc[t][2], sacc[t][3]));
        }
        #pragma unroll
        for (int off = 1; off < 4; off <<= 1) {
            vmaxA = fmaxf(vmaxA, __shfl_xor_sync(0xffffffffu, vmaxA, off));
            vmaxB = fmaxf(vmaxB, __shfl_xor_sync(0xffffffffu, vmaxB, off));
        }
        if ((lane & 3) == 0) {
            maxbuf[wn * 128 + rowA] = vmaxA;
            maxbuf[wn * 128 + rowB] = vmaxB;
        }
        barpair(1 + wm);
        float tmaxA = fmaxf(vmaxA, maxbuf[(wn ^ 1) * 128 + rowA]);
        float tmaxB = fmaxf(vmaxB, maxbuf[(wn ^ 1) * 128 + rowB]);
        float nmA = fmaxf(rmaxA, tmaxA), nmB = fmaxf(rmaxB, tmaxB);
        float alA = __expf(rmaxA - nmA), alB = __expf(rmaxB - nmB);
        rmaxA = nmA; rmaxB = nmB;
        float psA = 0.f, psB = 0.f;
        #pragma unroll
        for (int t = 0; t < 4; t++) {
            float p0 = __expf(sacc[t][0] - nmA), p1 = __expf(sacc[t][1] - nmA);
            float p2 = __expf(sacc[t][2] - nmB), p3 = __expf(sacc[t][3] - nmB);
            psA += p0 + p1; psB += p2 + p3;
            int col = wn * 32 + t * 8 + ((lane & 3) << 1);
            *(__half2*)&Ps[rowA * kKS + col] = __floats2half2_rn(p0, p1);
            *(__half2*)&Ps[rowB * kKS + col] = __floats2half2_rn(p2, p3);
        }
        #pragma unroll
        for (int c = 0; c < 4; c++)
            #pragma unroll
            for (int t = 0; t < 4; t++) {
                acc_o[c][t][0] *= alA; acc_o[c][t][1] *= alA;
                acc_o[c][t][2] *= alB; acc_o[c][t][3] *= alB;
            }
        #pragma unroll
        for (int off = 1; off < 4; off <<= 1) {
            psA += __shfl_xor_sync(0xffffffffu, psA, off);
            psB += __shfl_xor_sync(0xffffffffu, psB, off);
        }
        if ((lane & 3) == 0) {
            sumbuf[wn * 128 + rowA] = psA;
            sumbuf[wn * 128 + rowB] = psB;
        }
        barpair(1 + wm);
        rsumA = rsumA * alA + psA + sumbuf[(wn ^ 1) * 128 + rowA];
        rsumB = rsumB * alB + psB + sumbuf[(wn ^ 1) * 128 + rowB];

        // ======== O += P V^T (p fp16, v fp16) ========
        u32 pf[4][4];
        {
            int prow = wm * 16 + (lane & 15);
            int pcol = (lane >> 4) << 3;
            #pragma unroll
            for (int kk = 0; kk < 4; kk++)
                ldsm4(pf[kk], &Ps[prow * kKS + kk * 16 + pcol]);
        }
        int gpv = 0;
        #pragma unroll
        for (int ch = 0; ch < 4; ch++) {
            if ((ch & 1) == 0) {
                gpv = it * kChunksPerIter + 4 + (ch >> 1);
                if (gpv + 1 < kTotalChunks) cpwait1(); else cpwait0();
                __syncthreads();
                if (gi < kTotalChunks) { issue_chunk(gi); gi++; }
            }
            const __half* Vh = (const __half*)(smem + kOffStage + (gpv % 3) * kStageBytes
                                               + (ch & 1) * kStageHalf);
            int brow = wn * 32 + (lane & 7) + ((lane >> 4) << 3);
            int bcol = ((lane >> 3) & 1) << 3;
            #pragma unroll
            for (int kk = 0; kk < 4; kk++) {
                #pragma unroll
                for (int t2 = 0; t2 < 2; t2++) {
                    u32 vh4[4];
                    ldsm4(vh4, &Vh[(brow + t2 * 16) * kKS + kk * 16 + bcol]);
                    mma16816(acc_o[ch][t2 * 2 + 0], pf[kk], vh4[0], vh4[1]);
                    mma16816(acc_o[ch][t2 * 2 + 1], pf[kk], vh4[2], vh4[3]);
                }
            }
        }
    }

    // ======== epilogue: normalize, blend, store ========
    __syncthreads();
    float gamma = gamma_p[0];
    float invA = 1.0f / rsumA, invB = 1.0f / rsumB;

    #pragma unroll
    for (int ch = 0; ch < 4; ch++) {
        __syncthreads();
        #pragma unroll
        for (int t = 0; t < 4; t++) {
            int c0 = wn * 32 + t * 8 + ((lane & 3) << 1);
            Osm[c0 * kOS + rowA]       = acc_o[ch][t][0] * invA;
            Osm[(c0 + 1) * kOS + rowA] = acc_o[ch][t][1] * invA;
            Osm[c0 * kOS + rowB]       = acc_o[ch][t][2] * invB;
            Osm[(c0 + 1) * kOS + rowB] = acc_o[ch][t][3] * invB;
        }
        __syncthreads();
        int r = tid >> 3, c4 = (tid & 7) << 4;
        size_t gb = ((size_t)bat * CDIM + ch * 64 + r) * HWDIM + i0 + c4;
        #pragma unroll
        for (int u = 0; u < 4; u++) {
            float4 o4 = *(float4*)&Osm[r * kOS + c4 + u * 4];
            float4 a4 = *(const float4*)&a_in[gb + u * 4];
            float ov[4] = {o4.x, o4.y, o4.z, o4.w};
            float av[4] = {a4.x, a4.y, a4.z, a4.w};
            float rr[4];
            #pragma unroll
            for (int e = 0; e < 4; e++) {
                float m = m_s[c4 + u * 4 + e];
                rr[e] = av[e] * m + gamma * (1.0f - m) * ov[e];
            }
            *(float4*)&out[gb + u * 4] = make_float4(rr[0], rr[1], rr[2], rr[3]);
        }
    }
}

// ---------------- launch ----------------
extern "C" void kernel_launch(void* const* d_in, const int* in_sizes, int n_in,
                              void* d_out, int out_size)
{
    const float* a  = (const float*)d_in[0];
    const float* b  = (const float*)d_in[1];
    const float* c  = (const float*)d_in[2];
    const float* wq = (const float*)d_in[3];
    const float* bq = (const float*)d_in[4];
    const float* gq = (const float*)d_in[5];
    const float* wk = (const float*)d_in[6];
    const float* bk = (const float*)d_in[7];
    const float* gk = (const float*)d_in[8];
    const float* wv = (const float*)d_in[9];
    const float* bv = (const float*)d_in[10];
    const float* gv = (const float*)d_in[11];
    const float* gm = (const float*)d_in[12];
    float* out = (float*)d_out;

    cudaFuncSetAttribute(qkv_kernel, cudaFuncAttributeMaxDynamicSharedMemorySize, kQkvSmem);
    cudaFuncSetAttribute(attn_kernel, cudaFuncAttributeMaxDynamicSharedMemorySize, kSmemBytes);

    ws_kernel<<<CDIM, CDIM>>>(wq, gq, 0);
    ws_kernel<<<CDIM, CDIM>>>(wk, gk, 1);
    ws_kernel<<<CDIM, CDIM>>>(wv, gv, 2);

    dim3 g1(HWDIM / 128, CDIM / 128, 12);
    qkv_kernel<<<g1, 256, kQkvSmem>>>(a, b, bq, bk, bv);

    dim3 g2(HWDIM / kBM, BDIM);
    attn_kernel<<<g2, 512, kSmemBytes>>>(a, c, gm, out);
}

// round 11
// speedup vs baseline: 6.2778x; 1.2799x over previous
#include <cuda_runtime.h>
#include <cuda_fp16.h>
#include <cstdint>
#include <math.h>

typedef unsigned int u32;

#define CDIM  256
#define HWDIM 4096
#define BDIM  4

// ---------------- device scratch ----------------
__device__ __align__(16) __half g_wh[3][CDIM * CDIM];      // standardized W hi, [o][c]
__device__ __align__(16) __half g_wl[3][CDIM * CDIM];      // standardized W lo, [o][c]
__device__ __align__(16) __half g_qh[BDIM * HWDIM * CDIM]; // q hi  [b][i][c]
__device__ __align__(16) __half g_ql[BDIM * HWDIM * CDIM]; // q lo
__device__ __align__(16) __half g_kh[BDIM * HWDIM * CDIM]; // k fp16 [b][j][c]
__device__ __align__(16) __half g_vh[BDIM * CDIM * HWDIM]; // v fp16 [b][c][j]

// ---------------- mma / ldmatrix / cp.async helpers ----------------
__device__ __forceinline__ void ldsm4(u32* r, const void* p) {
    u32 addr = (u32)__cvta_generic_to_shared(p);
    asm volatile("ldmatrix.sync.aligned.m8n8.x4.shared.b16 {%0,%1,%2,%3}, [%4];"
                 : "=r"(r[0]), "=r"(r[1]), "=r"(r[2]), "=r"(r[3]) : "r"(addr));
}
__device__ __forceinline__ void ldsm4t(u32* r, const void* p) {
    u32 addr = (u32)__cvta_generic_to_shared(p);
    asm volatile("ldmatrix.sync.aligned.m8n8.x4.trans.shared.b16 {%0,%1,%2,%3}, [%4];"
                 : "=r"(r[0]), "=r"(r[1]), "=r"(r[2]), "=r"(r[3]) : "r"(addr));
}
__device__ __forceinline__ void mma16816(float* d, const u32* a, u32 b0, u32 b1) {
    asm volatile("mma.sync.aligned.m16n8k16.row.col.f32.f16.f16.f32 "
                 "{%0,%1,%2,%3}, {%4,%5,%6,%7}, {%8,%9}, {%0,%1,%2,%3};"
                 : "+f"(d[0]), "+f"(d[1]), "+f"(d[2]), "+f"(d[3])
                 : "r"(a[0]), "r"(a[1]), "r"(a[2]), "r"(a[3]), "r"(b0), "r"(b1));
}
__device__ __forceinline__ void cpasync16(u32 smem_dst, const void* gptr) {
    asm volatile("cp.async.cg.shared.global [%0], [%1], 16;" :: "r"(smem_dst), "l"(gptr));
}
__device__ __forceinline__ void cpcommit() { asm volatile("cp.async.commit_group;"); }
__device__ __forceinline__ void cpwait1()  { asm volatile("cp.async.wait_group 1;"); }
__device__ __forceinline__ void cpwait0()  { asm volatile("cp.async.wait_group 0;"); }
__device__ __forceinline__ void barpair(int id) {
    asm volatile("bar.sync %0, %1;" :: "r"(id), "r"(64) : "memory");
}

// ---------------- 1) weight standardization -> split fp16 [o][c] ----------------
__global__ void ws_kernel(const float* __restrict__ w,
                          const float* __restrict__ gain, int set)
{
    int o = blockIdx.x, c = threadIdx.x;
    float v = w[o * CDIM + c];
    float s = v, s2 = v * v;
    #pragma unroll
    for (int off = 16; off; off >>= 1) {
        s  += __shfl_xor_sync(0xffffffffu, s,  off);
        s2 += __shfl_xor_sync(0xffffffffu, s2, off);
    }
    __shared__ float red[16];
    int warp = c >> 5, lane = c & 31;
    if (lane == 0) { red[warp] = s; red[8 + warp] = s2; }
    __syncthreads();
    if (c == 0) {
        float ts = 0.f, ts2 = 0.f;
        #pragma unroll
        for (int i = 0; i < 8; i++) { ts += red[i]; ts2 += red[8 + i]; }
        red[0] = ts; red[8] = ts2;
    }
    __syncthreads();
    float mean = red[0] * (1.0f / CDIM);
    float var  = (red[8] - (float)CDIM * mean * mean) * (1.0f / (CDIM - 1));
    float scale = rsqrtf(fmaxf(var * (float)CDIM, 1e-4f)) * gain[o];
    float wsv = (v - mean) * scale;
    __half hh = __float2half_rn(wsv);
    __half ll = __float2half_rn(wsv - __half2float(hh));
    g_wh[set][o * CDIM + c] = hh;
    g_wl[set][o * CDIM + c] = ll;
}

// ---------------- 2) QKV GEMM on tensor cores (split fp16) ----------------
constexpr int kWS2 = 72;    // W smem stride (halves)
constexpr int kXS2 = 136;   // X smem stride (halves)
constexpr int kES2 = 136;   // epilogue stride (halves)
constexpr int kOffWl2 = 128 * kWS2 * 2;            // 18432
constexpr int kOffXh2 = 2 * kOffWl2;               // 36864
constexpr int kOffXl2 = kOffXh2 + 64 * kXS2 * 2;   // 54272
constexpr int kQkvSmem = kOffXl2 + 64 * kXS2 * 2;  // 71680

__global__ __launch_bounds__(256, 2) void qkv_kernel(
    const float* __restrict__ a_in, const float* __restrict__ b_in,
    const float* __restrict__ bq, const float* __restrict__ bk, const float* __restrict__ bv)
{
    extern __shared__ char sm2[];
    __half* Wh = (__half*)sm2;
    __half* Wl = (__half*)(sm2 + kOffWl2);
    __half* Xh = (__half*)(sm2 + kOffXh2);
    __half* Xl = (__half*)(sm2 + kOffXl2);
    __half* Eh = (__half*)sm2;
    __half* El = (__half*)(sm2 + 34816);

    int set = blockIdx.z >> 2;
    int bat = blockIdx.z & 3;
    const float* X    = ((set == 1) ? b_in : a_in) + (size_t)bat * CDIM * HWDIM;
    const float* bias = (set == 0) ? bq : (set == 1) ? bk : bv;
    const __half* GW_h = g_wh[set];
    const __half* GW_l = g_wl[set];

    int i0 = blockIdx.x * 128, o0 = blockIdx.y * 128;
    int tid = threadIdx.x, lane = tid & 31, wid = tid >> 5;
    int wm = wid & 3, wn = wid >> 2;

    float acc[2][8][4];
    #pragma unroll
    for (int mi = 0; mi < 2; mi++)
        #pragma unroll
        for (int f = 0; f < 8; f++)
            #pragma unroll
            for (int e = 0; e < 4; e++) acc[mi][f][e] = 0.f;

    for (int k0 = 0; k0 < CDIM; k0 += 64) {
        __syncthreads();
        #pragma unroll
        for (int q = 0; q < 4; q++) {
            int f = tid + q * 256;
            int r = f >> 3, c8 = (f & 7) << 3;
            size_t gb = (size_t)(o0 + r) * CDIM + k0 + c8;
            *(float4*)&Wh[r * kWS2 + c8] = *(const float4*)&GW_h[gb];
            *(float4*)&Wl[r * kWS2 + c8] = *(const float4*)&GW_l[gb];
        }
        #pragma unroll
        for (int q = 0; q < 8; q++) {
            int f = tid + q * 256;
            int r = f >> 5, c4 = (f & 31) << 2;
            float4 x4 = *(const float4*)&X[(size_t)(k0 + r) * HWDIM + i0 + c4];
            float xv[4] = {x4.x, x4.y, x4.z, x4.w};
            __half hs[4], ls[4];
            #pragma unroll
            for (int j = 0; j < 4; j++) {
                hs[j] = __float2half_rn(xv[j]);
                ls[j] = __float2half_rn(xv[j] - __half2float(hs[j]));
            }
            *(__half2*)&Xh[r * kXS2 + c4]     = __halves2half2(hs[0], hs[1]);
            *(__half2*)&Xh[r * kXS2 + c4 + 2] = __halves2half2(hs[2], hs[3]);
            *(__half2*)&Xl[r * kXS2 + c4]     = __halves2half2(ls[0], ls[1]);
            *(__half2*)&Xl[r * kXS2 + c4 + 2] = __halves2half2(ls[2], ls[3]);
        }
        __syncthreads();

        int arow0 = wm * 32 + (lane & 15);
        int acol  = (lane >> 4) << 3;
        int bk_r  = (lane & 7) + ((lane >> 3) & 1) * 8;
        int bn_c  = ((lane >> 4) & 1) * 8;
        #pragma unroll
        for (int ks = 0; ks < 4; ks++) {
            u32 ah[2][4], al[2][4];
            #pragma unroll
            for (int mi = 0; mi < 2; mi++) {
                ldsm4(ah[mi], &Wh[(arow0 + mi * 16) * kWS2 + ks * 16 + acol]);
                ldsm4(al[mi], &Wl[(arow0 + mi * 16) * kWS2 + ks * 16 + acol]);
            }
            #pragma unroll
            for (int nb = 0; nb < 4; nb++) {
                int n0 = wn * 64 + nb * 16;
                u32 bh[4], bl[4];
                ldsm4t(bh, &Xh[(ks * 16 + bk_r) * kXS2 + n0 + bn_c]);
                ldsm4t(bl, &Xl[(ks * 16 + bk_r) * kXS2 + n0 + bn_c]);
                #pragma unroll
                for (int mi = 0; mi < 2; mi++) {
                    #pragma unroll
                    for (int s = 0; s < 2; s++) {
                        float* d = acc[mi][nb * 2 + s];
                        mma16816(d, ah[mi], bh[s * 2], bh[s * 2 + 1]);
                        mma16816(d, ah[mi], bl[s * 2], bl[s * 2 + 1]);
                        mma16816(d, al[mi], bh[s * 2], bh[s * 2 + 1]);
                    }
                }
            }
        }
    }
    __syncthreads();

    // ---- epilogue: add bias, stage (lo only for q), coalesced store ----
    #pragma unroll
    for (int mi = 0; mi < 2; mi++) {
        #pragma unroll
        for (int p = 0; p < 2; p++) {
            int r = wm * 32 + mi * 16 + (lane >> 2) + p * 8;
            float bb = bias[o0 + r];
            #pragma unroll
            for (int f = 0; f < 8; f++) {
                int cbase = wn * 64 + (f >> 1) * 16 + (f & 1) * 8 + ((lane & 3) << 1);
                #pragma unroll
                for (int e = 0; e < 2; e++) {
                    float x = acc[mi][f][p * 2 + e] + bb;
                    __half hh = __float2half_rn(x);
                    if (set == 2) {
                        Eh[r * kES2 + cbase + e] = hh;
                    } else {
                        Eh[(cbase + e) * kES2 + r] = hh;
                        if (set == 0) {
                            __half ll = __float2half_rn(x - __half2float(hh));
                            El[(cbase + e) * kES2 + r] = ll;
                        }
                    }
                }
            }
        }
    }
    __syncthreads();

    __half* OH; size_t rbase; size_t rstride;
    if (set == 2) {
        OH = g_vh;
        rbase = ((size_t)bat * CDIM + o0) * HWDIM + i0;
        rstride = HWDIM;
    } else {
        OH = set ? g_kh : g_qh;
        rbase = ((size_t)bat * HWDIM + i0) * CDIM + o0;
        rstride = CDIM;
    }
    #pragma unroll
    for (int q = 0; q < 8; q++) {
        int f = tid + q * 256;
        int r = f >> 4, c8 = (f & 15) << 3;
        *(float4*)&OH[rbase + (size_t)r * rstride + c8] = *(float4*)&Eh[r * kES2 + c8];
        if (set == 0)
            *(float4*)&g_ql[rbase + (size_t)r * rstride + c8] = *(float4*)&El[r * kES2 + c8];
    }
}

// ---------------- 3) flash attention, BM=128, 4-group/iter cp.async pipeline ----------------
constexpr int kBM  = 128;
constexpr int kQS  = 264;
constexpr int kKS  = 72;
constexpr int kOS  = 132;
constexpr int kQhBytes    = kBM * kQS * 2;
constexpr int kOffQl      = kQhBytes;
constexpr int kStageHalf  = 64 * kKS * 2;            // 9216
constexpr int kStageBytes = 2 * kStageHalf;          // 18432
constexpr int kOffStage   = 2 * kQhBytes;
constexpr int kOffPs      = kOffStage + 3 * kStageBytes;
constexpr int kOffF32     = kOffPs + kBM * kKS * 2;
constexpr int kSmemBytes  = kOffF32 + 4096;
constexpr int kGroupsPerIter = 4;                    // Kpair0, Kpair1, Vpair0, Vpair1
constexpr int kTotalGroups   = (HWDIM / 64) * kGroupsPerIter;  // 256

__global__ __launch_bounds__(512) void attn_kernel(
    const float* __restrict__ a_in, const float* __restrict__ cm,
    const float* __restrict__ gamma_p, float* __restrict__ out)
{
    extern __shared__ char smem[];
    __half* Qh = (__half*)smem;
    __half* Ql = (__half*)(smem + kOffQl);
    __half* Ps = (__half*)(smem + kOffPs);
    float*  m_s    = (float*)(smem + kOffF32);
    float*  maxbuf = m_s + 128;   // [2][128]
    float*  sumbuf = m_s + 384;   // [2][128]
    float*  Osm    = (float*)smem;

    int bat = blockIdx.y;
    int i0  = blockIdx.x * kBM;
    int tid = threadIdx.x, lane = tid & 31, wid = tid >> 5;
    int wm = wid & 7, wn = wid >> 3;

    const __half* GQh = g_qh + (size_t)bat * HWDIM * CDIM;
    const __half* GQl = g_ql + (size_t)bat * HWDIM * CDIM;
    const __half* GKh = g_kh + (size_t)bat * HWDIM * CDIM;
    const __half* GVh = g_vh + (size_t)bat * CDIM * HWDIM;

    int cr = tid >> 3, cc8 = (tid & 7) << 3;
    auto issue_group = [&](int g) {
        int itj = g >> 2, c = g & 3;
        int j0 = itj * 64;
        u32 dH = (u32)__cvta_generic_to_shared(smem + kOffStage + (g % 3) * kStageBytes
                                               + (cr * kKS + cc8) * 2);
        if (c < 2) {
            // K c-pair: half0 = c cols [c*128, c*128+64), half1 = +64
            size_t o = (size_t)(j0 + cr) * CDIM + c * 128 + cc8;
            cpasync16(dH, GKh + o);
            cpasync16(dH + kStageHalf, GKh + o + 64);
        } else {
            int cpair = c - 2;
            size_t o0 = (size_t)(cpair * 128 + cr) * HWDIM + j0 + cc8;
            cpasync16(dH, GVh + o0);
            cpasync16(dH + kStageHalf, GVh + o0 + (size_t)64 * HWDIM);
        }
        cpcommit();
    };

    issue_group(0);
    issue_group(1);
    int gi = 2;

    if (tid < kBM) {
        int i = i0 + tid;
        m_s[tid] = cm[bat * 1024 + ((i >> 6) >> 1) * 32 + ((i & 63) >> 1)];
    }
    #pragma unroll
    for (int t = 0; t < 8; t++) {
        int idx = tid + t * 512;
        int r = idx >> 5, c8 = (idx & 31) << 3;
        size_t gb = (size_t)(i0 + r) * CDIM + c8;
        *(float4*)&Qh[r * kQS + c8] = *(const float4*)&GQh[gb];
        *(float4*)&Ql[r * kQS + c8] = *(const float4*)&GQl[gb];
    }
    __syncthreads();

    int rowA = wm * 16 + (lane >> 2), rowB = rowA + 8;
    float mA = m_s[rowA], mB = m_s[rowB];
    float rmaxA = -INFINITY, rmaxB = -INFINITY;
    float rsumA = 0.f, rsumB = 0.f;

    float acc_o[4][4][4];
    #pragma unroll
    for (int c = 0; c < 4; c++)
        #pragma unroll
        for (int t = 0; t < 4; t++)
            #pragma unroll
            for (int e = 0; e < 4; e++) acc_o[c][t][e] = 0.f;

    for (int it = 0; it < HWDIM / 64; it++) {
        // ======== S = Q^T K (q split, k fp16: 2 mmas) ========
        float sacc[4][4];
        #pragma unroll
        for (int t = 0; t < 4; t++)
            #pragma unroll
            for (int e = 0; e < 4; e++) sacc[t][e] = 0.f;

        int gk = 0;
        #pragma unroll
        for (int ch = 0; ch < 4; ch++) {
            if ((ch & 1) == 0) {
                gk = it * kGroupsPerIter + (ch >> 1);
                if (gk + 1 < kTotalGroups) cpwait1(); else cpwait0();
                __syncthreads();
                if (gi < kTotalGroups) { issue_group(gi); gi++; }
            }
            const __half* Kh = (const __half*)(smem + kOffStage + (gk % 3) * kStageBytes
                                               + (ch & 1) * kStageHalf);
            int arow = wm * 16 + (lane & 15);
            int acol = ch * 64 + ((lane >> 4) << 3);
            int brow = wn * 32 + (lane & 7) + ((lane >> 4) << 3);
            int bcol = ((lane >> 3) & 1) << 3;
            #pragma unroll
            for (int kk = 0; kk < 4; kk++) {
                u32 qa[4], qb[4];
                ldsm4(qa, &Qh[arow * kQS + acol + kk * 16]);
                ldsm4(qb, &Ql[arow * kQS + acol + kk * 16]);
                #pragma unroll
                for (int t2 = 0; t2 < 2; t2++) {
                    u32 kh4[4];
                    ldsm4(kh4, &Kh[(brow + t2 * 16) * kKS + kk * 16 + bcol]);
                    mma16816(sacc[t2 * 2 + 0], qa, kh4[0], kh4[1]);
                    mma16816(sacc[t2 * 2 + 0], qb, kh4[0], kh4[1]);
                    mma16816(sacc[t2 * 2 + 1], qa, kh4[2], kh4[3]);
                    mma16816(sacc[t2 * 2 + 1], qb, kh4[2], kh4[3]);
                }
            }
        }

        // ======== online softmax: pair-local (named barriers) ========
        float vmaxA = -INFINITY, vmaxB = -INFINITY;
        #pragma unroll
        for (int t = 0; t < 4; t++) {
            sacc[t][0] *= mA; sacc[t][1] *= mA;
            sacc[t][2] *= mB; sacc[t][3] *= mB;
            vmaxA = fmaxf(vmaxA, fmaxf(sacc[t][0], sacc[t][1]));
            vmaxB = fmaxf(vmaxB, fmaxf(sacc[t][2], sacc[t][3]));
        }
        #pragma unroll
        for (int off = 1; off < 4; off <<= 1) {
            vmaxA = fmaxf(vmaxA, __shfl_xor_sync(0xffffffffu, vmaxA, off));
            vmaxB = fmaxf(vmaxB, __shfl_xor_sync(0xffffffffu, vmaxB, off));
        }
        if ((lane & 3) == 0) {
            maxbuf[wn * 128 + rowA] = vmaxA;
            maxbuf[wn * 128 + rowB] = vmaxB;
        }
        barpair(1 + wm);
        float tmaxA = fmaxf(vmaxA, maxbuf[(wn ^ 1) * 128 + rowA]);
        float tmaxB = fmaxf(vmaxB, maxbuf[(wn ^ 1) * 128 + rowB]);
        float nmA = fmaxf(rmaxA, tmaxA), nmB = fmaxf(rmaxB, tmaxB);
        float alA = __expf(rmaxA - nmA), alB = __expf(rmaxB - nmB);
        rmaxA = nmA; rmaxB = nmB;
        float psA = 0.f, psB = 0.f;
        #pragma unroll
        for (int t = 0; t < 4; t++) {
            float p0 = __expf(sacc[t][0] - nmA), p1 = __expf(sacc[t][1] - nmA);
            float p2 = __expf(sacc[t][2] - nmB), p3 = __expf(sacc[t][3] - nmB);
            psA += p0 + p1; psB += p2 + p3;
            int col = wn * 32 + t * 8 + ((lane & 3) << 1);
            *(__half2*)&Ps[rowA * kKS + col] = __floats2half2_rn(p0, p1);
            *(__half2*)&Ps[rowB * kKS + col] = __floats2half2_rn(p2, p3);
        }
        #pragma unroll
        for (int c = 0; c < 4; c++)
            #pragma unroll
            for (int t = 0; t < 4; t++) {
                acc_o[c][t][0] *= alA; acc_o[c][t][1] *= alA;
                acc_o[c][t][2] *= alB; acc_o[c][t][3] *= alB;
            }
        #pragma unroll
        for (int off = 1; off < 4; off <<= 1) {
            psA += __shfl_xor_sync(0xffffffffu, psA, off);
            psB += __shfl_xor_sync(0xffffffffu, psB, off);
        }
        if ((lane & 3) == 0) {
            sumbuf[wn * 128 + rowA] = psA;
            sumbuf[wn * 128 + rowB] = psB;
        }
        barpair(1 + wm);
        rsumA = rsumA * alA + psA + sumbuf[(wn ^ 1) * 128 + rowA];
        rsumB = rsumB * alB + psB + sumbuf[(wn ^ 1) * 128 + rowB];

        // ======== O += P V^T (p fp16, v fp16) ========
        u32 pf[4][4];
        {
            int prow = wm * 16 + (lane & 15);
            int pcol = (lane >> 4) << 3;
            #pragma unroll
            for (int kk = 0; kk < 4; kk++)
                ldsm4(pf[kk], &Ps[prow * kKS + kk * 16 + pcol]);
        }
        int gpv = 0;
        #pragma unroll
        for (int ch = 0; ch < 4; ch++) {
            if ((ch & 1) == 0) {
                gpv = it * kGroupsPerIter + 2 + (ch >> 1);
                if (gpv + 1 < kTotalGroups) cpwait1(); else cpwait0();
                __syncthreads();
                if (gi < kTotalGroups) { issue_group(gi); gi++; }
            }
            const __half* Vh = (const __half*)(smem + kOffStage + (gpv % 3) * kStageBytes
                                               + (ch & 1) * kStageHalf);
            int brow = wn * 32 + (lane & 7) + ((lane >> 4) << 3);
            int bcol = ((lane >> 3) & 1) << 3;
            #pragma unroll
            for (int kk = 0; kk < 4; kk++) {
                #pragma unroll
                for (int t2 = 0; t2 < 2; t2++) {
                    u32 vh4[4];
                    ldsm4(vh4, &Vh[(brow + t2 * 16) * kKS + kk * 16 + bcol]);
                    mma16816(acc_o[ch][t2 * 2 + 0], pf[kk], vh4[0], vh4[1]);
                    mma16816(acc_o[ch][t2 * 2 + 1], pf[kk], vh4[2], vh4[3]);
                }
            }
        }
    }

    // ======== epilogue: normalize, blend, store ========
    __syncthreads();
    float gamma = gamma_p[0];
    float invA = 1.0f / rsumA, invB = 1.0f / rsumB;

    #pragma unroll
    for (int ch = 0; ch < 4; ch++) {
        __syncthreads();
        #pragma unroll
        for (int t = 0; t < 4; t++) {
            int c0 = wn * 32 + t * 8 + ((lane & 3) << 1);
            Osm[c0 * kOS + rowA]       = acc_o[ch][t][0] * invA;
            Osm[(c0 + 1) * kOS + rowA] = acc_o[ch][t][1] * invA;
            Osm[c0 * kOS + rowB]       = acc_o[ch][t][2] * invB;
            Osm[(c0 + 1) * kOS + rowB] = acc_o[ch][t][3] * invB;
        }
        __syncthreads();
        int r = tid >> 3, c4 = (tid & 7) << 4;
        size_t gb = ((size_t)bat * CDIM + ch * 64 + r) * HWDIM + i0 + c4;
        #pragma unroll
        for (int u = 0; u < 4; u++) {
            float4 o4 = *(float4*)&Osm[r * kOS + c4 + u * 4];
            float4 a4 = *(const float4*)&a_in[gb + u * 4];
            float ov[4] = {o4.x, o4.y, o4.z, o4.w};
            float av[4] = {a4.x, a4.y, a4.z, a4.w};
            float rr[4];
            #pragma unroll
            for (int e = 0; e < 4; e++) {
                float m = m_s[c4 + u * 4 + e];
                rr[e] = av[e] * m + gamma * (1.0f - m) * ov[e];
            }
            *(float4*)&out[gb + u * 4] = make_float4(rr[0], rr[1], rr[2], rr[3]);
        }
    }
}

// ---------------- launch ----------------
extern "C" void kernel_launch(void* const* d_in, const int* in_sizes, int n_in,
                              void* d_out, int out_size)
{
    const float* a  = (const float*)d_in[0];
    const float* b  = (const float*)d_in[1];
    const float* c  = (const float*)d_in[2];
    const float* wq = (const float*)d_in[3];
    const float* bq = (const float*)d_in[4];
    const float* gq = (const float*)d_in[5];
    const float* wk = (const float*)d_in[6];
    const float* bk = (const float*)d_in[7];
    const float* gk = (const float*)d_in[8];
    const float* wv = (const float*)d_in[9];
    const float* bv = (const float*)d_in[10];
    const float* gv = (const float*)d_in[11];
    const float* gm = (const float*)d_in[12];
    float* out = (float*)d_out;

    cudaFuncSetAttribute(qkv_kernel, cudaFuncAttributeMaxDynamicSharedMemorySize, kQkvSmem);
    cudaFuncSetAttribute(attn_kernel, cudaFuncAttributeMaxDynamicSharedMemorySize, kSmemBytes);

    ws_kernel<<<CDIM, CDIM>>>(wq, gq, 0);
    ws_kernel<<<CDIM, CDIM>>>(wk, gk, 1);
    ws_kernel<<<CDIM, CDIM>>>(wv, gv, 2);

    dim3 g1(HWDIM / 128, CDIM / 128, 12);
    qkv_kernel<<<g1, 256, kQkvSmem>>>(a, b, bq, bk, bv);

    dim3 g2(HWDIM / kBM, BDIM);
    attn_kernel<<<g2, 512, kSmemBytes>>>(a, c, gm, out);
}

// round 12
// speedup vs baseline: 6.3898x; 1.0178x over previous
#include <cuda_runtime.h>
#include <cuda_fp16.h>
#include <cstdint>
#include <math.h>

typedef unsigned int u32;

#define CDIM  256
#define HWDIM 4096
#define BDIM  4

// ---------------- device scratch ----------------
__device__ __align__(16) __half g_wh[3][CDIM * CDIM];      // standardized W hi, [o][c]
__device__ __align__(16) __half g_wl[3][CDIM * CDIM];      // standardized W lo, [o][c]
__device__ __align__(16) __half g_qh[BDIM * HWDIM * CDIM]; // q hi  [b][i][c]
__device__ __align__(16) __half g_ql[BDIM * HWDIM * CDIM]; // q lo
__device__ __align__(16) __half g_kh[BDIM * HWDIM * CDIM]; // k fp16 [b][j][c]
__device__ __align__(16) __half g_vh[BDIM * CDIM * HWDIM]; // v fp16 [b][c][j]

// ---------------- mma / ldmatrix / cp.async helpers ----------------
__device__ __forceinline__ void ldsm4(u32* r, const void* p) {
    u32 addr = (u32)__cvta_generic_to_shared(p);
    asm volatile("ldmatrix.sync.aligned.m8n8.x4.shared.b16 {%0,%1,%2,%3}, [%4];"
                 : "=r"(r[0]), "=r"(r[1]), "=r"(r[2]), "=r"(r[3]) : "r"(addr));
}
__device__ __forceinline__ void ldsm4t(u32* r, const void* p) {
    u32 addr = (u32)__cvta_generic_to_shared(p);
    asm volatile("ldmatrix.sync.aligned.m8n8.x4.trans.shared.b16 {%0,%1,%2,%3}, [%4];"
                 : "=r"(r[0]), "=r"(r[1]), "=r"(r[2]), "=r"(r[3]) : "r"(addr));
}
__device__ __forceinline__ void mma16816(float* d, const u32* a, u32 b0, u32 b1) {
    asm volatile("mma.sync.aligned.m16n8k16.row.col.f32.f16.f16.f32 "
                 "{%0,%1,%2,%3}, {%4,%5,%6,%7}, {%8,%9}, {%0,%1,%2,%3};"
                 : "+f"(d[0]), "+f"(d[1]), "+f"(d[2]), "+f"(d[3])
                 : "r"(a[0]), "r"(a[1]), "r"(a[2]), "r"(a[3]), "r"(b0), "r"(b1));
}
__device__ __forceinline__ void cpasync16(u32 smem_dst, const void* gptr) {
    asm volatile("cp.async.cg.shared.global [%0], [%1], 16;" :: "r"(smem_dst), "l"(gptr));
}
__device__ __forceinline__ void cpcommit() { asm volatile("cp.async.commit_group;"); }
__device__ __forceinline__ void cpwait1()  { asm volatile("cp.async.wait_group 1;"); }
__device__ __forceinline__ void cpwait0()  { asm volatile("cp.async.wait_group 0;"); }
__device__ __forceinline__ void barpair(int id) {
    asm volatile("bar.sync %0, %1;" :: "r"(id), "r"(64) : "memory");
}

// ---------------- 1) weight standardization -> split fp16 [o][c] ----------------
__global__ void ws_kernel(const float* __restrict__ w,
                          const float* __restrict__ gain, int set)
{
    int o = blockIdx.x, c = threadIdx.x;
    float v = w[o * CDIM + c];
    float s = v, s2 = v * v;
    #pragma unroll
    for (int off = 16; off; off >>= 1) {
        s  += __shfl_xor_sync(0xffffffffu, s,  off);
        s2 += __shfl_xor_sync(0xffffffffu, s2, off);
    }
    __shared__ float red[16];
    int warp = c >> 5, lane = c & 31;
    if (lane == 0) { red[warp] = s; red[8 + warp] = s2; }
    __syncthreads();
    if (c == 0) {
        float ts = 0.f, ts2 = 0.f;
        #pragma unroll
        for (int i = 0; i < 8; i++) { ts += red[i]; ts2 += red[8 + i]; }
        red[0] = ts; red[8] = ts2;
    }
    __syncthreads();
    float mean = red[0] * (1.0f / CDIM);
    float var  = (red[8] - (float)CDIM * mean * mean) * (1.0f / (CDIM - 1));
    float scale = rsqrtf(fmaxf(var * (float)CDIM, 1e-4f)) * gain[o];
    float wsv = (v - mean) * scale;
    __half hh = __float2half_rn(wsv);
    __half ll = __float2half_rn(wsv - __half2float(hh));
    g_wh[set][o * CDIM + c] = hh;
    g_wl[set][o * CDIM + c] = ll;
}

// ---------------- 2) QKV GEMM on tensor cores (split fp16) ----------------
constexpr int kWS2 = 72;    // W smem stride (halves)
constexpr int kXS2 = 136;   // X smem stride (halves)
constexpr int kES2 = 136;   // epilogue stride (halves)
constexpr int kOffWl2 = 128 * kWS2 * 2;            // 18432
constexpr int kOffXh2 = 2 * kOffWl2;               // 36864
constexpr int kOffXl2 = kOffXh2 + 64 * kXS2 * 2;   // 54272
constexpr int kQkvSmem = kOffXl2 + 64 * kXS2 * 2;  // 71680

__global__ __launch_bounds__(256, 2) void qkv_kernel(
    const float* __restrict__ a_in, const float* __restrict__ b_in,
    const float* __restrict__ bq, const float* __restrict__ bk, const float* __restrict__ bv)
{
    extern __shared__ char sm2[];
    __half* Wh = (__half*)sm2;
    __half* Wl = (__half*)(sm2 + kOffWl2);
    __half* Xh = (__half*)(sm2 + kOffXh2);
    __half* Xl = (__half*)(sm2 + kOffXl2);
    __half* Eh = (__half*)sm2;
    __half* El = (__half*)(sm2 + 34816);

    int set = blockIdx.z >> 2;
    int bat = blockIdx.z & 3;
    const float* X    = ((set == 1) ? b_in : a_in) + (size_t)bat * CDIM * HWDIM;
    const float* bias = (set == 0) ? bq : (set == 1) ? bk : bv;
    const __half* GW_h = g_wh[set];
    const __half* GW_l = g_wl[set];

    int i0 = blockIdx.x * 128, o0 = blockIdx.y * 128;
    int tid = threadIdx.x, lane = tid & 31, wid = tid >> 5;
    int wm = wid & 3, wn = wid >> 2;

    float acc[2][8][4];
    #pragma unroll
    for (int mi = 0; mi < 2; mi++)
        #pragma unroll
        for (int f = 0; f < 8; f++)
            #pragma unroll
            for (int e = 0; e < 4; e++) acc[mi][f][e] = 0.f;

    for (int k0 = 0; k0 < CDIM; k0 += 64) {
        __syncthreads();
        #pragma unroll
        for (int q = 0; q < 4; q++) {
            int f = tid + q * 256;
            int r = f >> 3, c8 = (f & 7) << 3;
            size_t gb = (size_t)(o0 + r) * CDIM + k0 + c8;
            *(float4*)&Wh[r * kWS2 + c8] = *(const float4*)&GW_h[gb];
            *(float4*)&Wl[r * kWS2 + c8] = *(const float4*)&GW_l[gb];
        }
        #pragma unroll
        for (int q = 0; q < 8; q++) {
            int f = tid + q * 256;
            int r = f >> 5, c4 = (f & 31) << 2;
            float4 x4 = *(const float4*)&X[(size_t)(k0 + r) * HWDIM + i0 + c4];
            float xv[4] = {x4.x, x4.y, x4.z, x4.w};
            __half hs[4], ls[4];
            #pragma unroll
            for (int j = 0; j < 4; j++) {
                hs[j] = __float2half_rn(xv[j]);
                ls[j] = __float2half_rn(xv[j] - __half2float(hs[j]));
            }
            *(__half2*)&Xh[r * kXS2 + c4]     = __halves2half2(hs[0], hs[1]);
            *(__half2*)&Xh[r * kXS2 + c4 + 2] = __halves2half2(hs[2], hs[3]);
            *(__half2*)&Xl[r * kXS2 + c4]     = __halves2half2(ls[0], ls[1]);
            *(__half2*)&Xl[r * kXS2 + c4 + 2] = __halves2half2(ls[2], ls[3]);
        }
        __syncthreads();

        int arow0 = wm * 32 + (lane & 15);
        int acol  = (lane >> 4) << 3;
        int bk_r  = (lane & 7) + ((lane >> 3) & 1) * 8;
        int bn_c  = ((lane >> 4) & 1) * 8;
        #pragma unroll
        for (int ks = 0; ks < 4; ks++) {
            u32 ah[2][4], al[2][4];
            #pragma unroll
            for (int mi = 0; mi < 2; mi++) {
                ldsm4(ah[mi], &Wh[(arow0 + mi * 16) * kWS2 + ks * 16 + acol]);
                ldsm4(al[mi], &Wl[(arow0 + mi * 16) * kWS2 + ks * 16 + acol]);
            }
            #pragma unroll
            for (int nb = 0; nb < 4; nb++) {
                int n0 = wn * 64 + nb * 16;
                u32 bh[4], bl[4];
                ldsm4t(bh, &Xh[(ks * 16 + bk_r) * kXS2 + n0 + bn_c]);
                ldsm4t(bl, &Xl[(ks * 16 + bk_r) * kXS2 + n0 + bn_c]);
                #pragma unroll
                for (int mi = 0; mi < 2; mi++) {
                    #pragma unroll
                    for (int s = 0; s < 2; s++) {
                        float* d = acc[mi][nb * 2 + s];
                        mma16816(d, ah[mi], bh[s * 2], bh[s * 2 + 1]);
                        mma16816(d, ah[mi], bl[s * 2], bl[s * 2 + 1]);
                        mma16816(d, al[mi], bh[s * 2], bh[s * 2 + 1]);
                    }
                }
            }
        }
    }
    __syncthreads();

    // ---- epilogue: add bias, stage (lo only for q), coalesced store ----
    #pragma unroll
    for (int mi = 0; mi < 2; mi++) {
        #pragma unroll
        for (int p = 0; p < 2; p++) {
            int r = wm * 32 + mi * 16 + (lane >> 2) + p * 8;
            float bb = bias[o0 + r];
            #pragma unroll
            for (int f = 0; f < 8; f++) {
                int cbase = wn * 64 + (f >> 1) * 16 + (f & 1) * 8 + ((lane & 3) << 1);
                #pragma unroll
                for (int e = 0; e < 2; e++) {
                    float x = acc[mi][f][p * 2 + e] + bb;
                    __half hh = __float2half_rn(x);
                    if (set == 2) {
                        Eh[r * kES2 + cbase + e] = hh;
                    } else {
                        Eh[(cbase + e) * kES2 + r] = hh;
                        if (set == 0) {
                            __half ll = __float2half_rn(x - __half2float(hh));
                            El[(cbase + e) * kES2 + r] = ll;
                        }
                    }
                }
            }
        }
    }
    __syncthreads();

    __half* OH; size_t rbase; size_t rstride;
    if (set == 2) {
        OH = g_vh;
        rbase = ((size_t)bat * CDIM + o0) * HWDIM + i0;
        rstride = HWDIM;
    } else {
        OH = set ? g_kh : g_qh;
        rbase = ((size_t)bat * HWDIM + i0) * CDIM + o0;
        rstride = CDIM;
    }
    #pragma unroll
    for (int q = 0; q < 8; q++) {
        int f = tid + q * 256;
        int r = f >> 4, c8 = (f & 15) << 3;
        *(float4*)&OH[rbase + (size_t)r * rstride + c8] = *(float4*)&Eh[r * kES2 + c8];
        if (set == 0)
            *(float4*)&g_ql[rbase + (size_t)r * rstride + c8] = *(float4*)&El[r * kES2 + c8];
    }
}

// ---------------- 3) flash attention, BM=128, base-2 softmax, lazy rescale ----------------
constexpr int kBM  = 128;
constexpr int kQS  = 264;
constexpr int kKS  = 72;
constexpr int kOS  = 132;
constexpr int kQhBytes    = kBM * kQS * 2;
constexpr int kOffQl      = kQhBytes;
constexpr int kStageHalf  = 64 * kKS * 2;            // 9216
constexpr int kStageBytes = 2 * kStageHalf;          // 18432
constexpr int kOffStage   = 2 * kQhBytes;
constexpr int kOffPs      = kOffStage + 3 * kStageBytes;
constexpr int kOffF32     = kOffPs + kBM * kKS * 2;
constexpr int kSmemBytes  = kOffF32 + 4096;
constexpr int kGroupsPerIter = 4;                    // Kpair0, Kpair1, Vpair0, Vpair1
constexpr int kTotalGroups   = (HWDIM / 64) * kGroupsPerIter;  // 256
constexpr float kL2E = 1.44269504088896340736f;

__global__ __launch_bounds__(512) void attn_kernel(
    const float* __restrict__ a_in, const float* __restrict__ cm,
    const float* __restrict__ gamma_p, float* __restrict__ out)
{
    extern __shared__ char smem[];
    __half* Qh = (__half*)smem;
    __half* Ql = (__half*)(smem + kOffQl);
    __half* Ps = (__half*)(smem + kOffPs);
    float*  m_s    = (float*)(smem + kOffF32);
    float*  maxbuf = m_s + 128;   // [2][128]
    float*  Osm    = (float*)smem;

    int bat = blockIdx.y;
    int i0  = blockIdx.x * kBM;
    int tid = threadIdx.x, lane = tid & 31, wid = tid >> 5;
    int wm = wid & 7, wn = wid >> 3;

    const __half* GQh = g_qh + (size_t)bat * HWDIM * CDIM;
    const __half* GQl = g_ql + (size_t)bat * HWDIM * CDIM;
    const __half* GKh = g_kh + (size_t)bat * HWDIM * CDIM;
    const __half* GVh = g_vh + (size_t)bat * CDIM * HWDIM;

    int cr = tid >> 3, cc8 = (tid & 7) << 3;
    auto issue_group = [&](int g) {
        int itj = g >> 2, c = g & 3;
        int j0 = itj * 64;
        u32 dH = (u32)__cvta_generic_to_shared(smem + kOffStage + (g % 3) * kStageBytes
                                               + (cr * kKS + cc8) * 2);
        if (c < 2) {
            size_t o = (size_t)(j0 + cr) * CDIM + c * 128 + cc8;
            cpasync16(dH, GKh + o);
            cpasync16(dH + kStageHalf, GKh + o + 64);
        } else {
            int cpair = c - 2;
            size_t o0 = (size_t)(cpair * 128 + cr) * HWDIM + j0 + cc8;
            cpasync16(dH, GVh + o0);
            cpasync16(dH + kStageHalf, GVh + o0 + (size_t)64 * HWDIM);
        }
        cpcommit();
    };

    issue_group(0);
    issue_group(1);
    int gi = 2;

    if (tid < kBM) {
        int i = i0 + tid;
        m_s[tid] = cm[bat * 1024 + ((i >> 6) >> 1) * 32 + ((i & 63) >> 1)];
    }
    #pragma unroll
    for (int t = 0; t < 8; t++) {
        int idx = tid + t * 512;
        int r = idx >> 5, c8 = (idx & 31) << 3;
        size_t gb = (size_t)(i0 + r) * CDIM + c8;
        *(float4*)&Qh[r * kQS + c8] = *(const float4*)&GQh[gb];
        *(float4*)&Ql[r * kQS + c8] = *(const float4*)&GQl[gb];
    }
    __syncthreads();

    int rowA = wm * 16 + (lane >> 2), rowB = rowA + 8;
    float mA2 = m_s[rowA] * kL2E, mB2 = m_s[rowB] * kL2E;   // mask folded with log2(e)
    float rmaxA = -INFINITY, rmaxB = -INFINITY;             // running max, base-2 domain
    float rsumA = 0.f, rsumB = 0.f;                         // lane-local partial sums

    float acc_o[4][4][4];
    #pragma unroll
    for (int c = 0; c < 4; c++)
        #pragma unroll
        for (int t = 0; t < 4; t++)
            #pragma unroll
            for (int e = 0; e < 4; e++) acc_o[c][t][e] = 0.f;

    for (int it = 0; it < HWDIM / 64; it++) {
        // ======== S = Q^T K (q split, k fp16: 2 mmas) ========
        float sacc[4][4];
        #pragma unroll
        for (int t = 0; t < 4; t++)
            #pragma unroll
            for (int e = 0; e < 4; e++) sacc[t][e] = 0.f;

        int gk = 0;
        #pragma unroll
        for (int ch = 0; ch < 4; ch++) {
            if ((ch & 1) == 0) {
                gk = it * kGroupsPerIter + (ch >> 1);
                if (gk + 1 < kTotalGroups) cpwait1(); else cpwait0();
                __syncthreads();
                if (gi < kTotalGroups) { issue_group(gi); gi++; }
            }
            const __half* Kh = (const __half*)(smem + kOffStage + (gk % 3) * kStageBytes
                                               + (ch & 1) * kStageHalf);
            int arow = wm * 16 + (lane & 15);
            int acol = ch * 64 + ((lane >> 4) << 3);
            int brow = wn * 32 + (lane & 7) + ((lane >> 4) << 3);
            int bcol = ((lane >> 3) & 1) << 3;
            #pragma unroll
            for (int kk = 0; kk < 4; kk++) {
                u32 qa[4], qb[4];
                ldsm4(qa, &Qh[arow * kQS + acol + kk * 16]);
                ldsm4(qb, &Ql[arow * kQS + acol + kk * 16]);
                #pragma unroll
                for (int t2 = 0; t2 < 2; t2++) {
                    u32 kh4[4];
                    ldsm4(kh4, &Kh[(brow + t2 * 16) * kKS + kk * 16 + bcol]);
                    mma16816(sacc[t2 * 2 + 0], qa, kh4[0], kh4[1]);
                    mma16816(sacc[t2 * 2 + 0], qb, kh4[0], kh4[1]);
                    mma16816(sacc[t2 * 2 + 1], qa, kh4[2], kh4[3]);
                    mma16816(sacc[t2 * 2 + 1], qb, kh4[2], kh4[3]);
                }
            }
        }

        // ======== online softmax (base-2, lazy rescale, deferred rsum) ========
        float vmaxA = -INFINITY, vmaxB = -INFINITY;
        #pragma unroll
        for (int t = 0; t < 4; t++) {
            sacc[t][0] *= mA2; sacc[t][1] *= mA2;
            sacc[t][2] *= mB2; sacc[t][3] *= mB2;
            vmaxA = fmaxf(vmaxA, fmaxf(sacc[t][0], sacc[t][1]));
            vmaxB = fmaxf(vmaxB, fmaxf(sacc[t][2], sacc[t][3]));
        }
        #pragma unroll
        for (int off = 1; off < 4; off <<= 1) {
            vmaxA = fmaxf(vmaxA, __shfl_xor_sync(0xffffffffu, vmaxA, off));
            vmaxB = fmaxf(vmaxB, __shfl_xor_sync(0xffffffffu, vmaxB, off));
        }
        if ((lane & 3) == 0) {
            maxbuf[wn * 128 + rowA] = vmaxA;
            maxbuf[wn * 128 + rowB] = vmaxB;
        }
        barpair(1 + wm);
        float nmA = fmaxf(rmaxA, fmaxf(vmaxA, maxbuf[(wn ^ 1) * 128 + rowA]));
        float nmB = fmaxf(rmaxB, fmaxf(vmaxB, maxbuf[(wn ^ 1) * 128 + rowB]));
        bool upA = nmA > rmaxA, upB = nmB > rmaxB;
        float alA = upA ? exp2f(rmaxA - nmA) : 1.0f;
        float alB = upB ? exp2f(rmaxB - nmB) : 1.0f;
        rmaxA = nmA; rmaxB = nmB;

        float psA = 0.f, psB = 0.f;
        #pragma unroll
        for (int t = 0; t < 4; t++) {
            float p0 = exp2f(sacc[t][0] - nmA), p1 = exp2f(sacc[t][1] - nmA);
            float p2 = exp2f(sacc[t][2] - nmB), p3 = exp2f(sacc[t][3] - nmB);
            psA += p0 + p1; psB += p2 + p3;
            int col = wn * 32 + t * 8 + ((lane & 3) << 1);
            *(__half2*)&Ps[rowA * kKS + col] = __floats2half2_rn(p0, p1);
            *(__half2*)&Ps[rowB * kKS + col] = __floats2half2_rn(p2, p3);
        }
        if (upA) {
            #pragma unroll
            for (int c = 0; c < 4; c++)
                #pragma unroll
                for (int t = 0; t < 4; t++) {
                    acc_o[c][t][0] *= alA; acc_o[c][t][1] *= alA;
                }
        }
        if (upB) {
            #pragma unroll
            for (int c = 0; c < 4; c++)
                #pragma unroll
                for (int t = 0; t < 4; t++) {
                    acc_o[c][t][2] *= alB; acc_o[c][t][3] *= alB;
                }
        }
        rsumA = rsumA * alA + psA;
        rsumB = rsumB * alB + psB;
        barpair(1 + wm);   // P tile ready across the warp pair

        // ======== O += P V^T (p fp16, v fp16) ========
        u32 pf[4][4];
        {
            int prow = wm * 16 + (lane & 15);
            int pcol = (lane >> 4) << 3;
            #pragma unroll
            for (int kk = 0; kk < 4; kk++)
                ldsm4(pf[kk], &Ps[prow * kKS + kk * 16 + pcol]);
        }
        int gpv = 0;
        #pragma unroll
        for (int ch = 0; ch < 4; ch++) {
            if ((ch & 1) == 0) {
                gpv = it * kGroupsPerIter + 2 + (ch >> 1);
                if (gpv + 1 < kTotalGroups) cpwait1(); else cpwait0();
                __syncthreads();
                if (gi < kTotalGroups) { issue_group(gi); gi++; }
            }
            const __half* Vh = (const __half*)(smem + kOffStage + (gpv % 3) * kStageBytes
                                               + (ch & 1) * kStageHalf);
            int brow = wn * 32 + (lane & 7) + ((lane >> 4) << 3);
            int bcol = ((lane >> 3) & 1) << 3;
            #pragma unroll
            for (int kk = 0; kk < 4; kk++) {
                #pragma unroll
                for (int t2 = 0; t2 < 2; t2++) {
                    u32 vh4[4];
                    ldsm4(vh4, &Vh[(brow + t2 * 16) * kKS + kk * 16 + bcol]);
                    mma16816(acc_o[ch][t2 * 2 + 0], pf[kk], vh4[0], vh4[1]);
                    mma16816(acc_o[ch][t2 * 2 + 1], pf[kk], vh4[2], vh4[3]);
                }
            }
        }
    }

    // ======== finalize rsum: quad reduce + pair exchange ========
    #pragma unroll
    for (int off = 1; off < 4; off <<= 1) {
        rsumA += __shfl_xor_sync(0xffffffffu, rsumA, off);
        rsumB += __shfl_xor_sync(0xffffffffu, rsumB, off);
    }
    if ((lane & 3) == 0) {
        maxbuf[wn * 128 + rowA] = rsumA;
        maxbuf[wn * 128 + rowB] = rsumB;
    }
    barpair(1 + wm);
    rsumA += maxbuf[(wn ^ 1) * 128 + rowA];
    rsumB += maxbuf[(wn ^ 1) * 128 + rowB];

    // ======== epilogue: normalize, blend, store ========
    __syncthreads();
    float gamma = gamma_p[0];
    float invA = 1.0f / rsumA, invB = 1.0f / rsumB;

    #pragma unroll
    for (int ch = 0; ch < 4; ch++) {
        __syncthreads();
        #pragma unroll
        for (int t = 0; t < 4; t++) {
            int c0 = wn * 32 + t * 8 + ((lane & 3) << 1);
            Osm[c0 * kOS + rowA]       = acc_o[ch][t][0] * invA;
            Osm[(c0 + 1) * kOS + rowA] = acc_o[ch][t][1] * invA;
            Osm[c0 * kOS + rowB]       = acc_o[ch][t][2] * invB;
            Osm[(c0 + 1) * kOS + rowB] = acc_o[ch][t][3] * invB;
        }
        __syncthreads();
        int r = tid >> 3, c4 = (tid & 7) << 4;
        size_t gb = ((size_t)bat * CDIM + ch * 64 + r) * HWDIM + i0 + c4;
        #pragma unroll
        for (int u = 0; u < 4; u++) {
            float4 o4 = *(float4*)&Osm[r * kOS + c4 + u * 4];
            float4 a4 = *(const float4*)&a_in[gb + u * 4];
            float ov[4] = {o4.x, o4.y, o4.z, o4.w};
            float av[4] = {a4.x, a4.y, a4.z, a4.w};
            float rr[4];
            #pragma unroll
            for (int e = 0; e < 4; e++) {
                float m = m_s[c4 + u * 4 + e];
                rr[e] = av[e] * m + gamma * (1.0f - m) * ov[e];
            }
            *(float4*)&out[gb + u * 4] = make_float4(rr[0], rr[1], rr[2], rr[3]);
        }
    }
}

// ---------------- launch ----------------
extern "C" void kernel_launch(void* const* d_in, const int* in_sizes, int n_in,
                              void* d_out, int out_size)
{
    const float* a  = (const float*)d_in[0];
    const float* b  = (const float*)d_in[1];
    const float* c  = (const float*)d_in[2];
    const float* wq = (const float*)d_in[3];
    const float* bq = (const float*)d_in[4];
    const float* gq = (const float*)d_in[5];
    const float* wk = (const float*)d_in[6];
    const float* bk = (const float*)d_in[7];
    const float* gk = (const float*)d_in[8];
    const float* wv = (const float*)d_in[9];
    const float* bv = (const float*)d_in[10];
    const float* gv = (const float*)d_in[11];
    const float* gm = (const float*)d_in[12];
    float* out = (float*)d_out;

    cudaFuncSetAttribute(qkv_kernel, cudaFuncAttributeMaxDynamicSharedMemorySize, kQkvSmem);
    cudaFuncSetAttribute(attn_kernel, cudaFuncAttributeMaxDynamicSharedMemorySize, kSmemBytes);

    ws_kernel<<<CDIM, CDIM>>>(wq, gq, 0);
    ws_kernel<<<CDIM, CDIM>>>(wk, gk, 1);
    ws_kernel<<<CDIM, CDIM>>>(wv, gv, 2);

    dim3 g1(HWDIM / 128, CDIM / 128, 12);
    qkv_kernel<<<g1, 256, kQkvSmem>>>(a, b, bq, bk, bv);

    dim3 g2(HWDIM / kBM, BDIM);
    attn_kernel<<<g2, 512, kSmemBytes>>>(a, c, gm, out);
}

// round 13
// speedup vs baseline: 7.3782x; 1.1547x over previous
#include <cuda_runtime.h>
#include <cuda_fp16.h>
#include <cstdint>
#include <math.h>

typedef unsigned int u32;

#define CDIM  256
#define HWDIM 4096
#define BDIM  4

// ---------------- device scratch ----------------
__device__ __align__(16) __half g_wh[3][CDIM * CDIM];      // standardized W hi, [o][c]
__device__ __align__(16) __half g_wl[3][CDIM * CDIM];      // standardized W lo, [o][c]
__device__ __align__(16) __half g_qh[BDIM * HWDIM * CDIM]; // q fp16 [b][i][c]
__device__ __align__(16) __half g_kh[BDIM * HWDIM * CDIM]; // k fp16 [b][j][c]
__device__ __align__(16) __half g_vh[BDIM * CDIM * HWDIM]; // v fp16 [b][c][j]

// ---------------- mma / ldmatrix / cp.async helpers ----------------
__device__ __forceinline__ void ldsm4(u32* r, const void* p) {
    u32 addr = (u32)__cvta_generic_to_shared(p);
    asm volatile("ldmatrix.sync.aligned.m8n8.x4.shared.b16 {%0,%1,%2,%3}, [%4];"
                 : "=r"(r[0]), "=r"(r[1]), "=r"(r[2]), "=r"(r[3]) : "r"(addr));
}
__device__ __forceinline__ void ldsm4t(u32* r, const void* p) {
    u32 addr = (u32)__cvta_generic_to_shared(p);
    asm volatile("ldmatrix.sync.aligned.m8n8.x4.trans.shared.b16 {%0,%1,%2,%3}, [%4];"
                 : "=r"(r[0]), "=r"(r[1]), "=r"(r[2]), "=r"(r[3]) : "r"(addr));
}
__device__ __forceinline__ void mma16816(float* d, const u32* a, u32 b0, u32 b1) {
    asm volatile("mma.sync.aligned.m16n8k16.row.col.f32.f16.f16.f32 "
                 "{%0,%1,%2,%3}, {%4,%5,%6,%7}, {%8,%9}, {%0,%1,%2,%3};"
                 : "+f"(d[0]), "+f"(d[1]), "+f"(d[2]), "+f"(d[3])
                 : "r"(a[0]), "r"(a[1]), "r"(a[2]), "r"(a[3]), "r"(b0), "r"(b1));
}
__device__ __forceinline__ void cpasync16(u32 smem_dst, const void* gptr) {
    asm volatile("cp.async.cg.shared.global [%0], [%1], 16;" :: "r"(smem_dst), "l"(gptr));
}
__device__ __forceinline__ void cpcommit() { asm volatile("cp.async.commit_group;"); }
__device__ __forceinline__ void cpwait1()  { asm volatile("cp.async.wait_group 1;"); }
__device__ __forceinline__ void cpwait0()  { asm volatile("cp.async.wait_group 0;"); }
__device__ __forceinline__ void barpair(int id) {
    asm volatile("bar.sync %0, %1;" :: "r"(id), "r"(64) : "memory");
}

// ---------------- 1) weight standardization -> split fp16 [o][c] ----------------
__global__ void ws_kernel(const float* __restrict__ w,
                          const float* __restrict__ gain, int set)
{
    int o = blockIdx.x, c = threadIdx.x;
    float v = w[o * CDIM + c];
    float s = v, s2 = v * v;
    #pragma unroll
    for (int off = 16; off; off >>= 1) {
        s  += __shfl_xor_sync(0xffffffffu, s,  off);
        s2 += __shfl_xor_sync(0xffffffffu, s2, off);
    }
    __shared__ float red[16];
    int warp = c >> 5, lane = c & 31;
    if (lane == 0) { red[warp] = s; red[8 + warp] = s2; }
    __syncthreads();
    if (c == 0) {
        float ts = 0.f, ts2 = 0.f;
        #pragma unroll
        for (int i = 0; i < 8; i++) { ts += red[i]; ts2 += red[8 + i]; }
        red[0] = ts; red[8] = ts2;
    }
    __syncthreads();
    float mean = red[0] * (1.0f / CDIM);
    float var  = (red[8] - (float)CDIM * mean * mean) * (1.0f / (CDIM - 1));
    float scale = rsqrtf(fmaxf(var * (float)CDIM, 1e-4f)) * gain[o];
    float wsv = (v - mean) * scale;
    __half hh = __float2half_rn(wsv);
    __half ll = __float2half_rn(wsv - __half2float(hh));
    g_wh[set][o * CDIM + c] = hh;
    g_wl[set][o * CDIM + c] = ll;
}

// ---------------- 2) QKV GEMM on tensor cores (split fp16 inputs, fp16 out) ----------------
constexpr int kWS2 = 72;    // W smem stride (halves)
constexpr int kXS2 = 136;   // X smem stride (halves)
constexpr int kES2 = 136;   // epilogue stride (halves)
constexpr int kOffWl2 = 128 * kWS2 * 2;            // 18432
constexpr int kOffXh2 = 2 * kOffWl2;               // 36864
constexpr int kOffXl2 = kOffXh2 + 64 * kXS2 * 2;   // 54272
constexpr int kQkvSmem = kOffXl2 + 64 * kXS2 * 2;  // 71680

__global__ __launch_bounds__(256, 2) void qkv_kernel(
    const float* __restrict__ a_in, const float* __restrict__ b_in,
    const float* __restrict__ bq, const float* __restrict__ bk, const float* __restrict__ bv)
{
    extern __shared__ char sm2[];
    __half* Wh = (__half*)sm2;
    __half* Wl = (__half*)(sm2 + kOffWl2);
    __half* Xh = (__half*)(sm2 + kOffXh2);
    __half* Xl = (__half*)(sm2 + kOffXl2);
    __half* Eh = (__half*)sm2;

    int set = blockIdx.z >> 2;
    int bat = blockIdx.z & 3;
    const float* X    = ((set == 1) ? b_in : a_in) + (size_t)bat * CDIM * HWDIM;
    const float* bias = (set == 0) ? bq : (set == 1) ? bk : bv;
    const __half* GW_h = g_wh[set];
    const __half* GW_l = g_wl[set];

    int i0 = blockIdx.x * 128, o0 = blockIdx.y * 128;
    int tid = threadIdx.x, lane = tid & 31, wid = tid >> 5;
    int wm = wid & 3, wn = wid >> 2;

    float acc[2][8][4];
    #pragma unroll
    for (int mi = 0; mi < 2; mi++)
        #pragma unroll
        for (int f = 0; f < 8; f++)
            #pragma unroll
            for (int e = 0; e < 4; e++) acc[mi][f][e] = 0.f;

    for (int k0 = 0; k0 < CDIM; k0 += 64) {
        __syncthreads();
        #pragma unroll
        for (int q = 0; q < 4; q++) {
            int f = tid + q * 256;
            int r = f >> 3, c8 = (f & 7) << 3;
            size_t gb = (size_t)(o0 + r) * CDIM + k0 + c8;
            *(float4*)&Wh[r * kWS2 + c8] = *(const float4*)&GW_h[gb];
            *(float4*)&Wl[r * kWS2 + c8] = *(const float4*)&GW_l[gb];
        }
        #pragma unroll
        for (int q = 0; q < 8; q++) {
            int f = tid + q * 256;
            int r = f >> 5, c4 = (f & 31) << 2;
            float4 x4 = *(const float4*)&X[(size_t)(k0 + r) * HWDIM + i0 + c4];
            float xv[4] = {x4.x, x4.y, x4.z, x4.w};
            __half hs[4], ls[4];
            #pragma unroll
            for (int j = 0; j < 4; j++) {
                hs[j] = __float2half_rn(xv[j]);
                ls[j] = __float2half_rn(xv[j] - __half2float(hs[j]));
            }
            *(__half2*)&Xh[r * kXS2 + c4]     = __halves2half2(hs[0], hs[1]);
            *(__half2*)&Xh[r * kXS2 + c4 + 2] = __halves2half2(hs[2], hs[3]);
            *(__half2*)&Xl[r * kXS2 + c4]     = __halves2half2(ls[0], ls[1]);
            *(__half2*)&Xl[r * kXS2 + c4 + 2] = __halves2half2(ls[2], ls[3]);
        }
        __syncthreads();

        int arow0 = wm * 32 + (lane & 15);
        int acol  = (lane >> 4) << 3;
        int bk_r  = (lane & 7) + ((lane >> 3) & 1) * 8;
        int bn_c  = ((lane >> 4) & 1) * 8;
        #pragma unroll
        for (int ks = 0; ks < 4; ks++) {
            u32 ah[2][4], al[2][4];
            #pragma unroll
            for (int mi = 0; mi < 2; mi++) {
                ldsm4(ah[mi], &Wh[(arow0 + mi * 16) * kWS2 + ks * 16 + acol]);
                ldsm4(al[mi], &Wl[(arow0 + mi * 16) * kWS2 + ks * 16 + acol]);
            }
            #pragma unroll
            for (int nb = 0; nb < 4; nb++) {
                int n0 = wn * 64 + nb * 16;
                u32 bh[4], bl[4];
                ldsm4t(bh, &Xh[(ks * 16 + bk_r) * kXS2 + n0 + bn_c]);
                ldsm4t(bl, &Xl[(ks * 16 + bk_r) * kXS2 + n0 + bn_c]);
                #pragma unroll
                for (int mi = 0; mi < 2; mi++) {
                    #pragma unroll
                    for (int s = 0; s < 2; s++) {
                        float* d = acc[mi][nb * 2 + s];
                        mma16816(d, ah[mi], bh[s * 2], bh[s * 2 + 1]);
                        mma16816(d, ah[mi], bl[s * 2], bl[s * 2 + 1]);
                        mma16816(d, al[mi], bh[s * 2], bh[s * 2 + 1]);
                    }
                }
            }
        }
    }
    __syncthreads();

    // ---- epilogue: add bias, fp16 stage, coalesced store ----
    #pragma unroll
    for (int mi = 0; mi < 2; mi++) {
        #pragma unroll
        for (int p = 0; p < 2; p++) {
            int r = wm * 32 + mi * 16 + (lane >> 2) + p * 8;
            float bb = bias[o0 + r];
            #pragma unroll
            for (int f = 0; f < 8; f++) {
                int cbase = wn * 64 + (f >> 1) * 16 + (f & 1) * 8 + ((lane & 3) << 1);
                #pragma unroll
                for (int e = 0; e < 2; e++) {
                    float x = acc[mi][f][p * 2 + e] + bb;
                    __half hh = __float2half_rn(x);
                    if (set == 2) Eh[r * kES2 + cbase + e] = hh;
                    else          Eh[(cbase + e) * kES2 + r] = hh;
                }
            }
        }
    }
    __syncthreads();

    __half* OH; size_t rbase; size_t rstride;
    if (set == 2) {
        OH = g_vh;
        rbase = ((size_t)bat * CDIM + o0) * HWDIM + i0;
        rstride = HWDIM;
    } else {
        OH = set ? g_kh : g_qh;
        rbase = ((size_t)bat * HWDIM + i0) * CDIM + o0;
        rstride = CDIM;
    }
    #pragma unroll
    for (int q = 0; q < 8; q++) {
        int f = tid + q * 256;
        int r = f >> 4, c8 = (f & 15) << 3;
        *(float4*)&OH[rbase + (size_t)r * rstride + c8] = *(float4*)&Eh[r * kES2 + c8];
    }
}

// ---------------- 3) flash attention, BM=128, all-fp16 operands ----------------
constexpr int kBM  = 128;
constexpr int kQS  = 264;
constexpr int kKS  = 72;
constexpr int kOS  = 132;
constexpr int kQhBytes    = kBM * kQS * 2;           // 67584
constexpr int kStageHalf  = 64 * kKS * 2;            // 9216
constexpr int kStageBytes = 2 * kStageHalf;          // 18432
constexpr int kOffStage   = kQhBytes;                // 67584
constexpr int kOffPs      = kOffStage + 3 * kStageBytes;   // 122880
constexpr int kOffF32     = kOffPs + kBM * kKS * 2;        // 141312
constexpr int kSmemBytes  = kOffF32 + 4096;                // 145408
constexpr int kGroupsPerIter = 4;                    // Kpair0, Kpair1, Vpair0, Vpair1
constexpr int kTotalGroups   = (HWDIM / 64) * kGroupsPerIter;  // 256
constexpr float kL2E = 1.44269504088896340736f;

__global__ __launch_bounds__(512) void attn_kernel(
    const float* __restrict__ a_in, const float* __restrict__ cm,
    const float* __restrict__ gamma_p, float* __restrict__ out)
{
    extern __shared__ char smem[];
    __half* Qh = (__half*)smem;
    __half* Ps = (__half*)(smem + kOffPs);
    float*  m_s    = (float*)(smem + kOffF32);
    float*  maxbuf = m_s + 128;   // [2][128]
    float*  Osm    = (float*)smem;

    int bat = blockIdx.y;
    int i0  = blockIdx.x * kBM;
    int tid = threadIdx.x, lane = tid & 31, wid = tid >> 5;
    int wm = wid & 7, wn = wid >> 3;

    const __half* GQh = g_qh + (size_t)bat * HWDIM * CDIM;
    const __half* GKh = g_kh + (size_t)bat * HWDIM * CDIM;
    const __half* GVh = g_vh + (size_t)bat * CDIM * HWDIM;

    int cr = tid >> 3, cc8 = (tid & 7) << 3;
    auto issue_group = [&](int g) {
        int itj = g >> 2, c = g & 3;
        int j0 = itj * 64;
        u32 dH = (u32)__cvta_generic_to_shared(smem + kOffStage + (g % 3) * kStageBytes
                                               + (cr * kKS + cc8) * 2);
        if (c < 2) {
            size_t o = (size_t)(j0 + cr) * CDIM + c * 128 + cc8;
            cpasync16(dH, GKh + o);
            cpasync16(dH + kStageHalf, GKh + o + 64);
        } else {
            int cpair = c - 2;
            size_t o0 = (size_t)(cpair * 128 + cr) * HWDIM + j0 + cc8;
            cpasync16(dH, GVh + o0);
            cpasync16(dH + kStageHalf, GVh + o0 + (size_t)64 * HWDIM);
        }
        cpcommit();
    };

    issue_group(0);
    issue_group(1);
    int gi = 2;

    if (tid < kBM) {
        int i = i0 + tid;
        m_s[tid] = cm[bat * 1024 + ((i >> 6) >> 1) * 32 + ((i & 63) >> 1)];
    }
    #pragma unroll
    for (int t = 0; t < 8; t++) {
        int idx = tid + t * 512;
        int r = idx >> 5, c8 = (idx & 31) << 3;
        *(float4*)&Qh[r * kQS + c8] = *(const float4*)&GQh[(size_t)(i0 + r) * CDIM + c8];
    }
    __syncthreads();

    int rowA = wm * 16 + (lane >> 2), rowB = rowA + 8;
    float mA2 = m_s[rowA] * kL2E, mB2 = m_s[rowB] * kL2E;
    float rmaxA = -INFINITY, rmaxB = -INFINITY;
    float rsumA = 0.f, rsumB = 0.f;

    float acc_o[4][4][4];
    #pragma unroll
    for (int c = 0; c < 4; c++)
        #pragma unroll
        for (int t = 0; t < 4; t++)
            #pragma unroll
            for (int e = 0; e < 4; e++) acc_o[c][t][e] = 0.f;

    for (int it = 0; it < HWDIM / 64; it++) {
        // ======== S = Q^T K (fp16 x fp16) ========
        float sacc[4][4];
        #pragma unroll
        for (int t = 0; t < 4; t++)
            #pragma unroll
            for (int e = 0; e < 4; e++) sacc[t][e] = 0.f;

        int gk = 0;
        #pragma unroll
        for (int ch = 0; ch < 4; ch++) {
            if ((ch & 1) == 0) {
                gk = it * kGroupsPerIter + (ch >> 1);
                if (gk + 1 < kTotalGroups) cpwait1(); else cpwait0();
                __syncthreads();
                if (gi < kTotalGroups) { issue_group(gi); gi++; }
            }
            const __half* Kh = (const __half*)(smem + kOffStage + (gk % 3) * kStageBytes
                                               + (ch & 1) * kStageHalf);
            int arow = wm * 16 + (lane & 15);
            int acol = ch * 64 + ((lane >> 4) << 3);
            int brow = wn * 32 + (lane & 7) + ((lane >> 4) << 3);
            int bcol = ((lane >> 3) & 1) << 3;
            #pragma unroll
            for (int kk = 0; kk < 4; kk++) {
                u32 qa[4];
                ldsm4(qa, &Qh[arow * kQS + acol + kk * 16]);
                #pragma unroll
                for (int t2 = 0; t2 < 2; t2++) {
                    u32 kh4[4];
                    ldsm4(kh4, &Kh[(brow + t2 * 16) * kKS + kk * 16 + bcol]);
                    mma16816(sacc[t2 * 2 + 0], qa, kh4[0], kh4[1]);
                    mma16816(sacc[t2 * 2 + 1], qa, kh4[2], kh4[3]);
                }
            }
        }

        // ======== online softmax (base-2, lazy rescale, deferred rsum) ========
        float vmaxA = -INFINITY, vmaxB = -INFINITY;
        #pragma unroll
        for (int t = 0; t < 4; t++) {
            sacc[t][0] *= mA2; sacc[t][1] *= mA2;
            sacc[t][2] *= mB2; sacc[t][3] *= mB2;
            vmaxA = fmaxf(vmaxA, fmaxf(sacc[t][0], sacc[t][1]));
            vmaxB = fmaxf(vmaxB, fmaxf(sacc[t][2], sacc[t][3]));
        }
        #pragma unroll
        for (int off = 1; off < 4; off <<= 1) {
            vmaxA = fmaxf(vmaxA, __shfl_xor_sync(0xffffffffu, vmaxA, off));
            vmaxB = fmaxf(vmaxB, __shfl_xor_sync(0xffffffffu, vmaxB, off));
        }
        if ((lane & 3) == 0) {
            maxbuf[wn * 128 + rowA] = vmaxA;
            maxbuf[wn * 128 + rowB] = vmaxB;
        }
        barpair(1 + wm);
        float nmA = fmaxf(rmaxA, fmaxf(vmaxA, maxbuf[(wn ^ 1) * 128 + rowA]));
        float nmB = fmaxf(rmaxB, fmaxf(vmaxB, maxbuf[(wn ^ 1) * 128 + rowB]));
        bool upA = nmA > rmaxA, upB = nmB > rmaxB;
        float alA = upA ? exp2f(rmaxA - nmA) : 1.0f;
        float alB = upB ? exp2f(rmaxB - nmB) : 1.0f;
        rmaxA = nmA; rmaxB = nmB;

        float psA = 0.f, psB = 0.f;
        #pragma unroll
        for (int t = 0; t < 4; t++) {
            float p0 = exp2f(sacc[t][0] - nmA), p1 = exp2f(sacc[t][1] - nmA);
            float p2 = exp2f(sacc[t][2] - nmB), p3 = exp2f(sacc[t][3] - nmB);
            psA += p0 + p1; psB += p2 + p3;
            int col = wn * 32 + t * 8 + ((lane & 3) << 1);
            *(__half2*)&Ps[rowA * kKS + col] = __floats2half2_rn(p0, p1);
            *(__half2*)&Ps[rowB * kKS + col] = __floats2half2_rn(p2, p3);
        }
        if (upA) {
            #pragma unroll
            for (int c = 0; c < 4; c++)
                #pragma unroll
                for (int t = 0; t < 4; t++) {
                    acc_o[c][t][0] *= alA; acc_o[c][t][1] *= alA;
                }
        }
        if (upB) {
            #pragma unroll
            for (int c = 0; c < 4; c++)
                #pragma unroll
                for (int t = 0; t < 4; t++) {
                    acc_o[c][t][2] *= alB; acc_o[c][t][3] *= alB;
                }
        }
        rsumA = rsumA * alA + psA;
        rsumB = rsumB * alB + psB;
        barpair(1 + wm);   // P tile ready across the warp pair

        // ======== O += P V^T ========
        u32 pf[4][4];
        {
            int prow = wm * 16 + (lane & 15);
            int pcol = (lane >> 4) << 3;
            #pragma unroll
            for (int kk = 0; kk < 4; kk++)
                ldsm4(pf[kk], &Ps[prow * kKS + kk * 16 + pcol]);
        }
        int gpv = 0;
        #pragma unroll
        for (int ch = 0; ch < 4; ch++) {
            if ((ch & 1) == 0) {
                gpv = it * kGroupsPerIter + 2 + (ch >> 1);
                if (gpv + 1 < kTotalGroups) cpwait1(); else cpwait0();
                __syncthreads();
                if (gi < kTotalGroups) { issue_group(gi); gi++; }
            }
            const __half* Vh = (const __half*)(smem + kOffStage + (gpv % 3) * kStageBytes
                                               + (ch & 1) * kStageHalf);
            int brow = wn * 32 + (lane & 7) + ((lane >> 4) << 3);
            int bcol = ((lane >> 3) & 1) << 3;
            #pragma unroll
            for (int kk = 0; kk < 4; kk++) {
                #pragma unroll
                for (int t2 = 0; t2 < 2; t2++) {
                    u32 vh4[4];
                    ldsm4(vh4, &Vh[(brow + t2 * 16) * kKS + kk * 16 + bcol]);
                    mma16816(acc_o[ch][t2 * 2 + 0], pf[kk], vh4[0], vh4[1]);
                    mma16816(acc_o[ch][t2 * 2 + 1], pf[kk], vh4[2], vh4[3]);
                }
            }
        }
    }

    // ======== finalize rsum ========
    #pragma unroll
    for (int off = 1; off < 4; off <<= 1) {
        rsumA += __shfl_xor_sync(0xffffffffu, rsumA, off);
        rsumB += __shfl_xor_sync(0xffffffffu, rsumB, off);
    }
    if ((lane & 3) == 0) {
        maxbuf[wn * 128 + rowA] = rsumA;
        maxbuf[wn * 128 + rowB] = rsumB;
    }
    barpair(1 + wm);
    rsumA += maxbuf[(wn ^ 1) * 128 + rowA];
    rsumB += maxbuf[(wn ^ 1) * 128 + rowB];

    // ======== epilogue: normalize, blend, store ========
    __syncthreads();
    float gamma = gamma_p[0];
    float invA = 1.0f / rsumA, invB = 1.0f / rsumB;

    #pragma unroll
    for (int ch = 0; ch < 4; ch++) {
        __syncthreads();
        #pragma unroll
        for (int t = 0; t < 4; t++) {
            int c0 = wn * 32 + t * 8 + ((lane & 3) << 1);
            Osm[c0 * kOS + rowA]       = acc_o[ch][t][0] * invA;
            Osm[(c0 + 1) * kOS + rowA] = acc_o[ch][t][1] * invA;
            Osm[c0 * kOS + rowB]       = acc_o[ch][t][2] * invB;
            Osm[(c0 + 1) * kOS + rowB] = acc_o[ch][t][3] * invB;
        }
        __syncthreads();
        int r = tid >> 3, c4 = (tid & 7) << 4;
        size_t gb = ((size_t)bat * CDIM + ch * 64 + r) * HWDIM + i0 + c4;
        #pragma unroll
        for (int u = 0; u < 4; u++) {
            float4 o4 = *(float4*)&Osm[r * kOS + c4 + u * 4];
            float4 a4 = *(const float4*)&a_in[gb + u * 4];
            float ov[4] = {o4.x, o4.y, o4.z, o4.w};
            float av[4] = {a4.x, a4.y, a4.z, a4.w};
            float rr[4];
            #pragma unroll
            for (int e = 0; e < 4; e++) {
                float m = m_s[c4 + u * 4 + e];
                rr[e] = av[e] * m + gamma * (1.0f - m) * ov[e];
            }
            *(float4*)&out[gb + u * 4] = make_float4(rr[0], rr[1], rr[2], rr[3]);
        }
    }
}

// ---------------- launch ----------------
extern "C" void kernel_launch(void* const* d_in, const int* in_sizes, int n_in,
                              void* d_out, int out_size)
{
    const float* a  = (const float*)d_in[0];
    const float* b  = (const float*)d_in[1];
    const float* c  = (const float*)d_in[2];
    const float* wq = (const float*)d_in[3];
    const float* bq = (const float*)d_in[4];
    const float* gq = (const float*)d_in[5];
    const float* wk = (const float*)d_in[6];
    const float* bk = (const float*)d_in[7];
    const float* gk = (const float*)d_in[8];
    const float* wv = (const float*)d_in[9];
    const float* bv = (const float*)d_in[10];
    const float* gv = (const float*)d_in[11];
    const float* gm = (const float*)d_in[12];
    float* out = (float*)d_out;

    cudaFuncSetAttribute(qkv_kernel, cudaFuncAttributeMaxDynamicSharedMemorySize, kQkvSmem);
    cudaFuncSetAttribute(attn_kernel, cudaFuncAttributeMaxDynamicSharedMemorySize, kSmemBytes);

    ws_kernel<<<CDIM, CDIM>>>(wq, gq, 0);
    ws_kernel<<<CDIM, CDIM>>>(wk, gk, 1);
    ws_kernel<<<CDIM, CDIM>>>(wv, gv, 2);

    dim3 g1(HWDIM / 128, CDIM / 128, 12);
    qkv_kernel<<<g1, 256, kQkvSmem>>>(a, b, bq, bk, bv);

    dim3 g2(HWDIM / kBM, BDIM);
    attn_kernel<<<g2, 512, kSmemBytes>>>(a, c, gm, out);
}